// round 5
// baseline (speedup 1.0000x reference)
#include <cuda_runtime.h>
#include <cuda_fp16.h>
#include <cuda_bf16.h>

#define T_SEQ 2048
#define NBATCH 16
#define DM 1024
#define HH 512

// ---------------- device scratch ----------------
__device__ float g_X[(size_t)T_SEQ * NBATCH * DM];
__device__ float g_XpF[(size_t)T_SEQ * NBATCH * 2048];
__device__ float g_XpB[(size_t)T_SEQ * NBATCH * 2048];
__device__ float g_H0f[(size_t)T_SEQ * NBATCH * HH];
__device__ float g_H0b[(size_t)T_SEQ * NBATCH * HH];
__device__ __half g_hh[2][2][NBATCH * HH];     // fp16 h exchange [dir][parity][b*512+u]
__device__ unsigned g_flag[2][32];             // per-direction per-block step flags

// ---------------- helpers ----------------
__device__ __forceinline__ unsigned FT(float x) {   // fp32 -> tf32 bits (rna)
    unsigned u;
    asm("cvt.rna.tf32.f32 %0, %1;" : "=r"(u) : "f"(x));
    return u;
}

__device__ __forceinline__ void mma8(float c[4], const unsigned a[4], const unsigned b[2]) {
    asm volatile(
        "mma.sync.aligned.m16n8k8.row.col.f32.tf32.tf32.f32 "
        "{%0,%1,%2,%3},{%4,%5,%6,%7},{%8,%9},{%0,%1,%2,%3};"
        : "+f"(c[0]), "+f"(c[1]), "+f"(c[2]), "+f"(c[3])
        : "r"(a[0]), "r"(a[1]), "r"(a[2]), "r"(a[3]), "r"(b[0]), "r"(b[1]));
}

__device__ __forceinline__ void mma16h(float c[4], const unsigned a[4],
                                       unsigned b0, unsigned b1) {
    asm volatile(
        "mma.sync.aligned.m16n8k16.row.col.f32.f16.f16.f32 "
        "{%0,%1,%2,%3},{%4,%5,%6,%7},{%8,%9},{%0,%1,%2,%3};"
        : "+f"(c[0]), "+f"(c[1]), "+f"(c[2]), "+f"(c[3])
        : "r"(a[0]), "r"(a[1]), "r"(a[2]), "r"(a[3]), "r"(b0), "r"(b1));
}

__device__ __forceinline__ void cpasync16(void* s, const void* g) {
    unsigned ss = (unsigned)__cvta_generic_to_shared(s);
    asm volatile("cp.async.ca.shared.global [%0], [%1], 16;" :: "r"(ss), "l"(g));
}
__device__ __forceinline__ void cp_commit() { asm volatile("cp.async.commit_group;"); }
__device__ __forceinline__ void cp_wait2() { asm volatile("cp.async.wait_group 2;"); }

__device__ __forceinline__ float sigm(float x) { return 1.f / (1.f + __expf(-x)); }
__device__ __forceinline__ float tanh_(float x) {
    float xc = fminf(fmaxf(x, -20.f), 20.f);
    float e = __expf(-2.f * xc);
    return (1.f - e) / (1.f + e);
}

// ---------------- embedding gather ----------------
__global__ void __launch_bounds__(256) embed_kernel(
    const int* __restrict__ ids, const float* __restrict__ tab, float* __restrict__ X) {
    int i = blockIdx.x * 256 + threadIdx.x;
    int q = i & 255, row = i >> 8;
    int b = row & 15, t = row >> 4;
    int id = ids[b * T_SEQ + t];
    reinterpret_cast<float4*>(X)[(size_t)row * 256 + q] =
        reinterpret_cast<const float4*>(tab)[(size_t)id * 256 + q];
}

// ---------------- pipelined TF32 GEMM (dynamic smem) ----------------
#define GA_STRIDE 20
#define GB_STRIDE 136
#define GA_TILE (128 * GA_STRIDE)
#define GB_TILE (16 * GB_STRIDE)
#define GEMM_SMEM_BYTES ((3 * GA_TILE + 3 * GB_TILE) * 4)

__global__ void __launch_bounds__(256) gemm_kernel(
    const float* __restrict__ A, const float* __restrict__ W,
    const float* __restrict__ bias, float* __restrict__ C, int K) {
    extern __shared__ __align__(16) float gsm[];
    float* As = gsm;
    float* Bs = gsm + 3 * GA_TILE;
    const int tid = threadIdx.x, lane = tid & 31, warp = tid >> 5;
    const int wm = warp >> 2, wn = warp & 3;
    const int gid = lane >> 2, tig = lane & 3;
    const int r0 = blockIdx.x * 128, n0 = blockIdx.y * 128;
    float acc[4][4][4] = {};

    const int ntiles = K >> 4;
    const int ar0 = tid >> 2, aq0 = (tid & 3) * 4;
    const int ar1 = (tid + 256) >> 2, aq1 = ((tid + 256) & 3) * 4;
    const int br0 = tid >> 5, bq0 = (tid & 31) * 4;
    const int br1 = (tid + 256) >> 5, bq1 = ((tid + 256) & 31) * 4;

#define COPY_TILE(s, kt)                                                                     \
    do {                                                                                     \
        int k0_ = (kt) << 4;                                                                 \
        cpasync16(As + (s) * GA_TILE + ar0 * GA_STRIDE + aq0,                                \
                  A + (size_t)(r0 + ar0) * K + k0_ + aq0);                                   \
        cpasync16(As + (s) * GA_TILE + ar1 * GA_STRIDE + aq1,                                \
                  A + (size_t)(r0 + ar1) * K + k0_ + aq1);                                   \
        cpasync16(Bs + (s) * GB_TILE + br0 * GB_STRIDE + bq0,                                \
                  W + (size_t)(k0_ + br0) * 2048 + n0 + bq0);                                \
        cpasync16(Bs + (s) * GB_TILE + br1 * GB_STRIDE + bq1,                                \
                  W + (size_t)(k0_ + br1) * 2048 + n0 + bq1);                                \
    } while (0)

    COPY_TILE(0, 0); cp_commit();
    COPY_TILE(1, 1); cp_commit();
    COPY_TILE(2, 2); cp_commit();

    for (int t = 0; t < ntiles; ++t) {
        int s = t % 3;
        const float* Asb = As + s * GA_TILE;
        const float* Bsb = Bs + s * GB_TILE;
        cp_wait2();
        __syncthreads();
#pragma unroll
        for (int kk = 0; kk < 16; kk += 8) {
            unsigned a[4][4], bb[4][2];
#pragma unroll
            for (int mt = 0; mt < 4; ++mt) {
                int m = wm * 64 + mt * 16;
                a[mt][0] = FT(Asb[(m + gid) * GA_STRIDE + kk + tig]);
                a[mt][1] = FT(Asb[(m + gid + 8) * GA_STRIDE + kk + tig]);
                a[mt][2] = FT(Asb[(m + gid) * GA_STRIDE + kk + tig + 4]);
                a[mt][3] = FT(Asb[(m + gid + 8) * GA_STRIDE + kk + tig + 4]);
            }
#pragma unroll
            for (int nt = 0; nt < 4; ++nt) {
                int nb = wn * 32 + nt * 8 + gid;
                bb[nt][0] = FT(Bsb[(kk + tig) * GB_STRIDE + nb]);
                bb[nt][1] = FT(Bsb[(kk + tig + 4) * GB_STRIDE + nb]);
            }
#pragma unroll
            for (int mt = 0; mt < 4; ++mt)
#pragma unroll
                for (int nt = 0; nt < 4; ++nt)
                    mma8(acc[mt][nt], a[mt], bb[nt]);
        }
        __syncthreads();
        if (t + 3 < ntiles) COPY_TILE(s, t + 3);
        cp_commit();
    }
#undef COPY_TILE

#pragma unroll
    for (int mt = 0; mt < 4; ++mt) {
#pragma unroll
        for (int nt = 0; nt < 4; ++nt) {
#pragma unroll
            for (int e = 0; e < 4; ++e) {
                int row = r0 + wm * 64 + mt * 16 + gid + ((e >> 1) * 8);
                int col = n0 + wn * 32 + nt * 8 + 2 * tig + (e & 1);
                float v = acc[mt][nt][e] + bias[col];
                int tt = row >> 4, b = row & 15;
                int gt = col >> 9, u = col & 511;
                size_t addr = (((size_t)tt * 32 + (u >> 4)) * 64 + gt * 16 + (u & 15)) * 16 + b;
                C[addr] = v;
            }
        }
    }
}

// ---------------- zero barrier/state ----------------
__global__ void __launch_bounds__(256) zero_kernel() {
    int i = blockIdx.x * 256 + threadIdx.x;
    if (i < 2 * 2 * NBATCH * HH / 2) ((unsigned*)g_hh)[i] = 0u;   // halves as u32 pairs
    if (i < 64) ((unsigned*)g_flag)[i] = 0u;
}

// ---------------- persistent LSTM scan (fp16 recurrent mma) ----------------
// 64 blocks: [0,32)=fwd, [32,64)=bwd. Block owns 16 units -> 64 gate cols.
// gates^T (64x16) = Wh^T (64x512) @ h^T (512x16) via mma.m16n8k16.f16.f32.
// 8 warps: mt = warp>>1 (m16 tile), kh = warp&1 (K half of 256).
// smem: A frags (half2, frag-major) 64KB | hs [16][520] half | Gb [2][64][17] f32
#define SCAN_SMEM_BYTES (65536 + 16640 + 8704)

__global__ void __launch_bounds__(256, 1) scan_kernel(
    const float* __restrict__ WhF, const float* __restrict__ WhB,
    const float* __restrict__ XpF, const float* __restrict__ XpB,
    float* __restrict__ outF, float* __restrict__ outB, int mode) {
    extern __shared__ __align__(16) char smraw[];
    unsigned* Wa = (unsigned*)smraw;                       // 16384 half2 regs
    __half* hs = (__half*)(smraw + 65536);                 // [16][520]
    float* Gb = (float*)(smraw + 65536 + 16640);           // [2][64][17]

    const int dir = blockIdx.x >> 5;
    const int blk = blockIdx.x & 31;
    const int u0 = blk * 16;
    const float* Wh = dir ? WhB : WhF;
    const float* Xp = dir ? XpB : XpF;
    float* out = dir ? outB : outF;

    const int tid = threadIdx.x, lane = tid & 31, warp = tid >> 5;
    const int mt = warp >> 1, kh = warp & 1;
    const int gid = lane >> 2, tig = lane & 3;

    // W_h slice -> fp16 fragment-major smem
    for (int idx = tid; idx < 16384; idx += 256) {
        int reg = idx & 3;
        int ln = (idx >> 2) & 31;
        int ks = (idx >> 7) & 15;
        int khh = (idx >> 11) & 1;
        int mtt = idx >> 12;
        int lgid = ln >> 2, ltig = ln & 3;
        int m = mtt * 16 + ((reg & 1) << 3) + lgid;
        int k = khh * 256 + ks * 16 + ((reg >> 1) << 3) + 2 * ltig;
        int col = ((m >> 4) << 9) + u0 + (m & 15);
        __half2 v = __floats2half2_rn(Wh[(size_t)k * 2048 + col],
                                      Wh[(size_t)(k + 1) * 2048 + col]);
        Wa[idx] = *(unsigned*)&v;
    }
    __syncthreads();

    const int ej = tid & 15, eb = tid >> 4;
    const int q = tid & 63;            // uint4 index within an h row
    const int b0_ = tid >> 6;          // batch row base (0..3), +4 per iter
    const int myflag = q >> 1;         // producer block of this k-range
    unsigned* flags = g_flag[dir];

    float c_state = 0.f;
    const unsigned* Afb = Wa + ((mt * 2 + kh) * 16) * 128 + lane * 4;
    float* Gp = Gb + kh * 1088;

    for (int s = 0; s < T_SEQ; ++s) {
        int t = dir ? (T_SEQ - 1 - s) : s;

        const float* xp = Xp + ((size_t)t * 32 + blk) * 1024;
        float xi = xp[(0 * 16 + ej) * 16 + eb];
        float xg = xp[(1 * 16 + ej) * 16 + eb];
        float xf = xp[(2 * 16 + ej) * 16 + eb];
        float xo = xp[(3 * 16 + ej) * 16 + eb];

        // wait for the producer of my k-range (acquire), then stage h into smem
        if (s > 0) {
            unsigned v;
            do {
                asm volatile("ld.acquire.gpu.global.u32 %0, [%1];"
                             : "=r"(v) : "l"(flags + myflag));
            } while ((int)v < s);
        }
        const uint4* hsrc = (const uint4*)g_hh[dir][s & 1];
#pragma unroll
        for (int i = 0; i < 4; ++i) {
            int b = b0_ + i * 4;
            uint4 val = hsrc[b * 64 + q];
            *(uint4*)(hs + b * 520 + q * 8) = val;
        }
        __syncthreads();

        // recurrent GEMM (fp16, fp32 accum)
        float c0[4] = {}, c1[4] = {};
        const int k0b = kh * 256;
#pragma unroll
        for (int ks = 0; ks < 16; ++ks) {
            uint4 av = *(const uint4*)(Afb + ks * 128);
            unsigned a[4] = {av.x, av.y, av.z, av.w};
            int k0 = k0b + ks * 16;
            unsigned b00 = *(const unsigned*)(hs + gid * 520 + k0 + 2 * tig);
            unsigned b01 = *(const unsigned*)(hs + gid * 520 + k0 + 2 * tig + 8);
            unsigned b10 = *(const unsigned*)(hs + (8 + gid) * 520 + k0 + 2 * tig);
            unsigned b11 = *(const unsigned*)(hs + (8 + gid) * 520 + k0 + 2 * tig + 8);
            mma16h(c0, a, b00, b01);
            mma16h(c1, a, b10, b11);
        }

        // k-half partials to disjoint buffers; summed at read
        int rb = mt * 16 + gid;
        Gp[rb * 17 + 2 * tig] = c0[0];
        Gp[rb * 17 + 2 * tig + 1] = c0[1];
        Gp[(rb + 8) * 17 + 2 * tig] = c0[2];
        Gp[(rb + 8) * 17 + 2 * tig + 1] = c0[3];
        Gp[rb * 17 + 8 + 2 * tig] = c1[0];
        Gp[rb * 17 + 8 + 2 * tig + 1] = c1[1];
        Gp[(rb + 8) * 17 + 8 + 2 * tig] = c1[2];
        Gp[(rb + 8) * 17 + 8 + 2 * tig + 1] = c1[3];
        __syncthreads();

        float gi = Gb[(0 * 16 + ej) * 17 + eb] + Gb[1088 + (0 * 16 + ej) * 17 + eb] + xi;
        float gg = Gb[(1 * 16 + ej) * 17 + eb] + Gb[1088 + (1 * 16 + ej) * 17 + eb] + xg;
        float gf = Gb[(2 * 16 + ej) * 17 + eb] + Gb[1088 + (2 * 16 + ej) * 17 + eb] + xf;
        float go = Gb[(3 * 16 + ej) * 17 + eb] + Gb[1088 + (3 * 16 + ej) * 17 + eb] + xo;
        float fgate = sigm(gf + 1.0f);
        c_state = fgate * c_state + sigm(gi) * tanh_(gg);
        float h = sigm(go) * tanh_(c_state);

        g_hh[dir][(s + 1) & 1][eb * 512 + u0 + ej] = __float2half(h);
        if (mode == 0)
            out[((size_t)t * 16 + eb) * 512 + u0 + ej] = h;
        else
            out[((size_t)eb * 2048 + t) * 1024 + dir * 512 + u0 + ej] = h;

        __threadfence();
        __syncthreads();
        if (tid == 0) {
            unsigned nv = (unsigned)(s + 1);
            asm volatile("st.release.gpu.global.u32 [%0], %1;" :: "l"(flags + blk), "r"(nv));
        }
    }
}

// ---------------- launch ----------------
extern "C" void kernel_launch(void* const* d_in, const int* in_sizes, int n_in,
                              void* d_out, int out_size) {
    const int* ids = (const int*)d_in[0];
    const float* tab = (const float*)d_in[1];
    const float* fW0 = (const float*)d_in[2];
    const float* fb0 = (const float*)d_in[3];
    const float* fW1 = (const float*)d_in[4];
    const float* fb1 = (const float*)d_in[5];
    const float* bW0 = (const float*)d_in[6];
    const float* bb0 = (const float*)d_in[7];
    const float* bW1 = (const float*)d_in[8];
    const float* bb1 = (const float*)d_in[9];
    float* out = (float*)d_out;

    cudaFuncSetAttribute(scan_kernel, cudaFuncAttributeMaxDynamicSharedMemorySize,
                         SCAN_SMEM_BYTES);
    cudaFuncSetAttribute(gemm_kernel, cudaFuncAttributeMaxDynamicSharedMemorySize,
                         GEMM_SMEM_BYTES);

    float *X, *XpF, *XpB, *H0f, *H0b;
    cudaGetSymbolAddress((void**)&X, g_X);
    cudaGetSymbolAddress((void**)&XpF, g_XpF);
    cudaGetSymbolAddress((void**)&XpB, g_XpB);
    cudaGetSymbolAddress((void**)&H0f, g_H0f);
    cudaGetSymbolAddress((void**)&H0b, g_H0b);

    embed_kernel<<<(T_SEQ * NBATCH * 256) / 256, 256>>>(ids, tab, X);

    dim3 gg(256, 16);
    gemm_kernel<<<gg, 256, GEMM_SMEM_BYTES>>>(X, fW0, fb0, XpF, 1024);
    gemm_kernel<<<gg, 256, GEMM_SMEM_BYTES>>>(X, bW0, bb0, XpB, 1024);
    zero_kernel<<<128, 256>>>();
    scan_kernel<<<64, 256, SCAN_SMEM_BYTES>>>(fW0 + 1024 * 2048, bW0 + 1024 * 2048,
                                              XpF, XpB, H0f, H0b, 0);
    gemm_kernel<<<gg, 256, GEMM_SMEM_BYTES>>>(H0f, fW1, fb1, XpF, 512);
    gemm_kernel<<<gg, 256, GEMM_SMEM_BYTES>>>(H0b, bW1, bb1, XpB, 512);
    zero_kernel<<<128, 256>>>();
    scan_kernel<<<64, 256, SCAN_SMEM_BYTES>>>(fW1 + 512 * 2048, bW1 + 512 * 2048,
                                              XpF, XpB, out, out, 1);
}

// round 6
// speedup vs baseline: 1.3788x; 1.3788x over previous
#include <cuda_runtime.h>
#include <cuda_fp16.h>
#include <cuda_bf16.h>

#define T_SEQ 2048
#define NBATCH 16
#define DM 1024
#define HH 512

// ---------------- device scratch ----------------
__device__ float g_X[(size_t)T_SEQ * NBATCH * DM];
__device__ float g_XpF[(size_t)T_SEQ * NBATCH * 2048];
__device__ float g_XpB[(size_t)T_SEQ * NBATCH * 2048];
__device__ float g_H0f[(size_t)T_SEQ * NBATCH * HH];
__device__ float g_H0b[(size_t)T_SEQ * NBATCH * HH];
__device__ __half g_hh[2][2][NBATCH * HH];     // fp16 h exchange [dir][parity][b*512+u]
__device__ unsigned g_cnt[2];                  // per-direction barrier counters

// ---------------- helpers ----------------
__device__ __forceinline__ unsigned FT(float x) {   // fp32 -> tf32 bits (rna)
    unsigned u;
    asm("cvt.rna.tf32.f32 %0, %1;" : "=r"(u) : "f"(x));
    return u;
}

__device__ __forceinline__ void mma8(float c[4], const unsigned a[4], const unsigned b[2]) {
    asm volatile(
        "mma.sync.aligned.m16n8k8.row.col.f32.tf32.tf32.f32 "
        "{%0,%1,%2,%3},{%4,%5,%6,%7},{%8,%9},{%0,%1,%2,%3};"
        : "+f"(c[0]), "+f"(c[1]), "+f"(c[2]), "+f"(c[3])
        : "r"(a[0]), "r"(a[1]), "r"(a[2]), "r"(a[3]), "r"(b[0]), "r"(b[1]));
}

__device__ __forceinline__ void mma16h(float c[4], const unsigned a[4],
                                       unsigned b0, unsigned b1) {
    asm volatile(
        "mma.sync.aligned.m16n8k16.row.col.f32.f16.f16.f32 "
        "{%0,%1,%2,%3},{%4,%5,%6,%7},{%8,%9},{%0,%1,%2,%3};"
        : "+f"(c[0]), "+f"(c[1]), "+f"(c[2]), "+f"(c[3])
        : "r"(a[0]), "r"(a[1]), "r"(a[2]), "r"(a[3]), "r"(b0), "r"(b1));
}

__device__ __forceinline__ void cpasync16(void* s, const void* g) {
    unsigned ss = (unsigned)__cvta_generic_to_shared(s);
    asm volatile("cp.async.ca.shared.global [%0], [%1], 16;" :: "r"(ss), "l"(g));
}
__device__ __forceinline__ void cp_commit() { asm volatile("cp.async.commit_group;"); }
__device__ __forceinline__ void cp_wait2() { asm volatile("cp.async.wait_group 2;"); }

__device__ __forceinline__ float sigm(float x) { return 1.f / (1.f + __expf(-x)); }
__device__ __forceinline__ float tanh_(float x) {
    float xc = fminf(fmaxf(x, -20.f), 20.f);
    float e = __expf(-2.f * xc);
    return (1.f - e) / (1.f + e);
}

// ---------------- embedding gather ----------------
__global__ void __launch_bounds__(256) embed_kernel(
    const int* __restrict__ ids, const float* __restrict__ tab, float* __restrict__ X) {
    int i = blockIdx.x * 256 + threadIdx.x;
    int q = i & 255, row = i >> 8;
    int b = row & 15, t = row >> 4;
    int id = ids[b * T_SEQ + t];
    reinterpret_cast<float4*>(X)[(size_t)row * 256 + q] =
        reinterpret_cast<const float4*>(tab)[(size_t)id * 256 + q];
}

// ---------------- pipelined TF32 GEMM (dynamic smem) ----------------
#define GA_STRIDE 20
#define GB_STRIDE 136
#define GA_TILE (128 * GA_STRIDE)
#define GB_TILE (16 * GB_STRIDE)
#define GEMM_SMEM_BYTES ((3 * GA_TILE + 3 * GB_TILE) * 4)

__global__ void __launch_bounds__(256) gemm_kernel(
    const float* __restrict__ A, const float* __restrict__ W,
    const float* __restrict__ bias, float* __restrict__ C, int K) {
    extern __shared__ __align__(16) float gsm[];
    float* As = gsm;
    float* Bs = gsm + 3 * GA_TILE;
    const int tid = threadIdx.x, lane = tid & 31, warp = tid >> 5;
    const int wm = warp >> 2, wn = warp & 3;
    const int gid = lane >> 2, tig = lane & 3;
    const int r0 = blockIdx.x * 128, n0 = blockIdx.y * 128;
    float acc[4][4][4] = {};

    const int ntiles = K >> 4;
    const int ar0 = tid >> 2, aq0 = (tid & 3) * 4;
    const int ar1 = (tid + 256) >> 2, aq1 = ((tid + 256) & 3) * 4;
    const int br0 = tid >> 5, bq0 = (tid & 31) * 4;
    const int br1 = (tid + 256) >> 5, bq1 = ((tid + 256) & 31) * 4;

#define COPY_TILE(s, kt)                                                                     \
    do {                                                                                     \
        int k0_ = (kt) << 4;                                                                 \
        cpasync16(As + (s) * GA_TILE + ar0 * GA_STRIDE + aq0,                                \
                  A + (size_t)(r0 + ar0) * K + k0_ + aq0);                                   \
        cpasync16(As + (s) * GA_TILE + ar1 * GA_STRIDE + aq1,                                \
                  A + (size_t)(r0 + ar1) * K + k0_ + aq1);                                   \
        cpasync16(Bs + (s) * GB_TILE + br0 * GB_STRIDE + bq0,                                \
                  W + (size_t)(k0_ + br0) * 2048 + n0 + bq0);                                \
        cpasync16(Bs + (s) * GB_TILE + br1 * GB_STRIDE + bq1,                                \
                  W + (size_t)(k0_ + br1) * 2048 + n0 + bq1);                                \
    } while (0)

    COPY_TILE(0, 0); cp_commit();
    COPY_TILE(1, 1); cp_commit();
    COPY_TILE(2, 2); cp_commit();

    for (int t = 0; t < ntiles; ++t) {
        int s = t % 3;
        const float* Asb = As + s * GA_TILE;
        const float* Bsb = Bs + s * GB_TILE;
        cp_wait2();
        __syncthreads();
#pragma unroll
        for (int kk = 0; kk < 16; kk += 8) {
            unsigned a[4][4], bb[4][2];
#pragma unroll
            for (int mt = 0; mt < 4; ++mt) {
                int m = wm * 64 + mt * 16;
                a[mt][0] = FT(Asb[(m + gid) * GA_STRIDE + kk + tig]);
                a[mt][1] = FT(Asb[(m + gid + 8) * GA_STRIDE + kk + tig]);
                a[mt][2] = FT(Asb[(m + gid) * GA_STRIDE + kk + tig + 4]);
                a[mt][3] = FT(Asb[(m + gid + 8) * GA_STRIDE + kk + tig + 4]);
            }
#pragma unroll
            for (int nt = 0; nt < 4; ++nt) {
                int nb = wn * 32 + nt * 8 + gid;
                bb[nt][0] = FT(Bsb[(kk + tig) * GB_STRIDE + nb]);
                bb[nt][1] = FT(Bsb[(kk + tig + 4) * GB_STRIDE + nb]);
            }
#pragma unroll
            for (int mt = 0; mt < 4; ++mt)
#pragma unroll
                for (int nt = 0; nt < 4; ++nt)
                    mma8(acc[mt][nt], a[mt], bb[nt]);
        }
        __syncthreads();
        if (t + 3 < ntiles) COPY_TILE(s, t + 3);
        cp_commit();
    }
#undef COPY_TILE

#pragma unroll
    for (int mt = 0; mt < 4; ++mt) {
#pragma unroll
        for (int nt = 0; nt < 4; ++nt) {
#pragma unroll
            for (int e = 0; e < 4; ++e) {
                int row = r0 + wm * 64 + mt * 16 + gid + ((e >> 1) * 8);
                int col = n0 + wn * 32 + nt * 8 + 2 * tig + (e & 1);
                float v = acc[mt][nt][e] + bias[col];
                int tt = row >> 4, b = row & 15;
                int gt = col >> 9, u = col & 511;
                size_t addr = (((size_t)tt * 32 + (u >> 4)) * 64 + gt * 16 + (u & 15)) * 16 + b;
                C[addr] = v;
            }
        }
    }
}

// ---------------- zero barrier/state ----------------
__global__ void __launch_bounds__(256) zero_kernel() {
    int i = blockIdx.x * 256 + threadIdx.x;
    if (i < 2 * 2 * NBATCH * HH / 2) ((unsigned*)g_hh)[i] = 0u;
    if (i < 2) g_cnt[i] = 0u;
}

// ---------------- persistent LSTM scan (fp16 recurrent mma, R4 barrier) ----------------
#define SCAN_SMEM_BYTES (65536 + 16640 + 8704)

__global__ void __launch_bounds__(256, 1) scan_kernel(
    const float* __restrict__ WhF, const float* __restrict__ WhB,
    const float* __restrict__ XpF, const float* __restrict__ XpB,
    float* __restrict__ outF, float* __restrict__ outB, int mode) {
    extern __shared__ __align__(16) char smraw[];
    unsigned* Wa = (unsigned*)smraw;                       // 16384 half2 regs
    __half* hs = (__half*)(smraw + 65536);                 // [16][520]
    float* Gb = (float*)(smraw + 65536 + 16640);           // [2][64][17]

    const int dir = blockIdx.x >> 5;
    const int blk = blockIdx.x & 31;
    const int u0 = blk * 16;
    const float* Wh = dir ? WhB : WhF;
    const float* Xp = dir ? XpB : XpF;
    float* out = dir ? outB : outF;

    const int tid = threadIdx.x, lane = tid & 31, warp = tid >> 5;
    const int mt = warp >> 1, kh = warp & 1;
    const int gid = lane >> 2, tig = lane & 3;

    // W_h slice -> fp16 fragment-major smem
    for (int idx = tid; idx < 16384; idx += 256) {
        int reg = idx & 3;
        int ln = (idx >> 2) & 31;
        int ks = (idx >> 7) & 15;
        int khh = (idx >> 11) & 1;
        int mtt = idx >> 12;
        int lgid = ln >> 2, ltig = ln & 3;
        int m = mtt * 16 + ((reg & 1) << 3) + lgid;
        int k = khh * 256 + ks * 16 + ((reg >> 1) << 3) + 2 * ltig;
        int col = ((m >> 4) << 9) + u0 + (m & 15);
        __half2 v = __floats2half2_rn(Wh[(size_t)k * 2048 + col],
                                      Wh[(size_t)(k + 1) * 2048 + col]);
        Wa[idx] = *(unsigned*)&v;
    }
    __syncthreads();

    const int ej = tid & 15, eb = tid >> 4;
    const int q = tid & 63;            // uint4 index within an h row
    const int b0_ = tid >> 6;          // batch row base (0..3), +4 per iter

    float c_state = 0.f;
    unsigned* bar = &g_cnt[dir];
    const unsigned* Afb = Wa + ((mt * 2 + kh) * 16) * 128 + lane * 4;
    float* Gp = Gb + kh * 1088;

    for (int s = 0; s < T_SEQ; ++s) {
        int t = dir ? (T_SEQ - 1 - s) : s;

        const float* xp = Xp + ((size_t)t * 32 + blk) * 1024;
        float xi = xp[(0 * 16 + ej) * 16 + eb];
        float xg = xp[(1 * 16 + ej) * 16 + eb];
        float xf = xp[(2 * 16 + ej) * 16 + eb];
        float xo = xp[(3 * 16 + ej) * 16 + eb];

        // stage h into smem (barrier at end of previous step guarantees readiness)
        const uint4* hsrc = (const uint4*)g_hh[dir][s & 1];
#pragma unroll
        for (int i = 0; i < 4; ++i) {
            int b = b0_ + i * 4;
            uint4 val = hsrc[b * 64 + q];
            *(uint4*)(hs + b * 520 + q * 8) = val;
        }
        __syncthreads();

        // recurrent GEMM (fp16, fp32 accum)
        float c0[4] = {}, c1[4] = {};
        const int k0b = kh * 256;
#pragma unroll
        for (int ks = 0; ks < 16; ++ks) {
            uint4 av = *(const uint4*)(Afb + ks * 128);
            unsigned a[4] = {av.x, av.y, av.z, av.w};
            int k0 = k0b + ks * 16;
            unsigned b00 = *(const unsigned*)(hs + gid * 520 + k0 + 2 * tig);
            unsigned b01 = *(const unsigned*)(hs + gid * 520 + k0 + 2 * tig + 8);
            unsigned b10 = *(const unsigned*)(hs + (8 + gid) * 520 + k0 + 2 * tig);
            unsigned b11 = *(const unsigned*)(hs + (8 + gid) * 520 + k0 + 2 * tig + 8);
            mma16h(c0, a, b00, b01);
            mma16h(c1, a, b10, b11);
        }

        // k-half partials to disjoint buffers; summed at read
        int rb = mt * 16 + gid;
        Gp[rb * 17 + 2 * tig] = c0[0];
        Gp[rb * 17 + 2 * tig + 1] = c0[1];
        Gp[(rb + 8) * 17 + 2 * tig] = c0[2];
        Gp[(rb + 8) * 17 + 2 * tig + 1] = c0[3];
        Gp[rb * 17 + 8 + 2 * tig] = c1[0];
        Gp[rb * 17 + 8 + 2 * tig + 1] = c1[1];
        Gp[(rb + 8) * 17 + 8 + 2 * tig] = c1[2];
        Gp[(rb + 8) * 17 + 8 + 2 * tig + 1] = c1[3];
        __syncthreads();

        float gi = Gb[(0 * 16 + ej) * 17 + eb] + Gb[1088 + (0 * 16 + ej) * 17 + eb] + xi;
        float gg = Gb[(1 * 16 + ej) * 17 + eb] + Gb[1088 + (1 * 16 + ej) * 17 + eb] + xg;
        float gf = Gb[(2 * 16 + ej) * 17 + eb] + Gb[1088 + (2 * 16 + ej) * 17 + eb] + xf;
        float go = Gb[(3 * 16 + ej) * 17 + eb] + Gb[1088 + (3 * 16 + ej) * 17 + eb] + xo;
        float fgate = sigm(gf + 1.0f);
        c_state = fgate * c_state + sigm(gi) * tanh_(gg);
        float h = sigm(go) * tanh_(c_state);

        g_hh[dir][(s + 1) & 1][eb * 512 + u0 + ej] = __float2half(h);
        if (mode == 0)
            out[((size_t)t * 16 + eb) * 512 + u0 + ej] = h;
        else
            out[((size_t)eb * 2048 + t) * 1024 + dir * 512 + u0 + ej] = h;

        // R4-proven inter-block barrier: single counter, tid0-only traffic
        __threadfence();
        __syncthreads();
        if (tid == 0) {
            atomicAdd(bar, 1u);
            unsigned tgt = 32u * (unsigned)(s + 1);
            volatile unsigned* p = bar;
            while (*p < tgt) {}
        }
        __syncthreads();
        __threadfence();
    }
}

// ---------------- launch ----------------
extern "C" void kernel_launch(void* const* d_in, const int* in_sizes, int n_in,
                              void* d_out, int out_size) {
    const int* ids = (const int*)d_in[0];
    const float* tab = (const float*)d_in[1];
    const float* fW0 = (const float*)d_in[2];
    const float* fb0 = (const float*)d_in[3];
    const float* fW1 = (const float*)d_in[4];
    const float* fb1 = (const float*)d_in[5];
    const float* bW0 = (const float*)d_in[6];
    const float* bb0 = (const float*)d_in[7];
    const float* bW1 = (const float*)d_in[8];
    const float* bb1 = (const float*)d_in[9];
    float* out = (float*)d_out;

    cudaFuncSetAttribute(scan_kernel, cudaFuncAttributeMaxDynamicSharedMemorySize,
                         SCAN_SMEM_BYTES);
    cudaFuncSetAttribute(gemm_kernel, cudaFuncAttributeMaxDynamicSharedMemorySize,
                         GEMM_SMEM_BYTES);

    float *X, *XpF, *XpB, *H0f, *H0b;
    cudaGetSymbolAddress((void**)&X, g_X);
    cudaGetSymbolAddress((void**)&XpF, g_XpF);
    cudaGetSymbolAddress((void**)&XpB, g_XpB);
    cudaGetSymbolAddress((void**)&H0f, g_H0f);
    cudaGetSymbolAddress((void**)&H0b, g_H0b);

    embed_kernel<<<(T_SEQ * NBATCH * 256) / 256, 256>>>(ids, tab, X);

    dim3 gg(256, 16);
    gemm_kernel<<<gg, 256, GEMM_SMEM_BYTES>>>(X, fW0, fb0, XpF, 1024);
    gemm_kernel<<<gg, 256, GEMM_SMEM_BYTES>>>(X, bW0, bb0, XpB, 1024);
    zero_kernel<<<128, 256>>>();
    scan_kernel<<<64, 256, SCAN_SMEM_BYTES>>>(fW0 + 1024 * 2048, bW0 + 1024 * 2048,
                                              XpF, XpB, H0f, H0b, 0);
    gemm_kernel<<<gg, 256, GEMM_SMEM_BYTES>>>(H0f, fW1, fb1, XpF, 512);
    gemm_kernel<<<gg, 256, GEMM_SMEM_BYTES>>>(H0b, bW1, bb1, XpB, 512);
    zero_kernel<<<128, 256>>>();
    scan_kernel<<<64, 256, SCAN_SMEM_BYTES>>>(fW1 + 512 * 2048, bW1 + 512 * 2048,
                                              XpF, XpB, out, out, 1);
}

// round 7
// speedup vs baseline: 2.9351x; 2.1288x over previous
#include <cuda_runtime.h>
#include <cuda_fp16.h>
#include <cuda_bf16.h>

#define T_SEQ 2048
#define NBATCH 16
#define DM 1024
#define HH 512

// ---------------- device scratch ----------------
__device__ float g_X[(size_t)T_SEQ * NBATCH * DM];
__device__ float g_XpF[(size_t)T_SEQ * NBATCH * 2048];
__device__ float g_XpB[(size_t)T_SEQ * NBATCH * 2048];
__device__ __half g_h0[2][2][NBATCH * HH];     // layer0 h exchange [dir][parity]
__device__ __half g_h1[2][2][NBATCH * HH];     // layer1 h exchange
__device__ unsigned g_cnt[2];                  // per-direction barrier counters

// ---------------- helpers ----------------
__device__ __forceinline__ unsigned FT(float x) {
    unsigned u;
    asm("cvt.rna.tf32.f32 %0, %1;" : "=r"(u) : "f"(x));
    return u;
}

__device__ __forceinline__ void mma8(float c[4], const unsigned a[4], const unsigned b[2]) {
    asm volatile(
        "mma.sync.aligned.m16n8k8.row.col.f32.tf32.tf32.f32 "
        "{%0,%1,%2,%3},{%4,%5,%6,%7},{%8,%9},{%0,%1,%2,%3};"
        : "+f"(c[0]), "+f"(c[1]), "+f"(c[2]), "+f"(c[3])
        : "r"(a[0]), "r"(a[1]), "r"(a[2]), "r"(a[3]), "r"(b[0]), "r"(b[1]));
}

__device__ __forceinline__ void mma16h(float c[4], const unsigned a[4],
                                       unsigned b0, unsigned b1) {
    asm volatile(
        "mma.sync.aligned.m16n8k16.row.col.f32.f16.f16.f32 "
        "{%0,%1,%2,%3},{%4,%5,%6,%7},{%8,%9},{%0,%1,%2,%3};"
        : "+f"(c[0]), "+f"(c[1]), "+f"(c[2]), "+f"(c[3])
        : "r"(a[0]), "r"(a[1]), "r"(a[2]), "r"(a[3]), "r"(b0), "r"(b1));
}

__device__ __forceinline__ void cpasync16(void* s, const void* g) {
    unsigned ss = (unsigned)__cvta_generic_to_shared(s);
    asm volatile("cp.async.ca.shared.global [%0], [%1], 16;" :: "r"(ss), "l"(g));
}
__device__ __forceinline__ void cp_commit() { asm volatile("cp.async.commit_group;"); }
__device__ __forceinline__ void cp_wait2() { asm volatile("cp.async.wait_group 2;"); }

__device__ __forceinline__ float sigm(float x) { return 1.f / (1.f + __expf(-x)); }
__device__ __forceinline__ float tanh_(float x) {
    float xc = fminf(fmaxf(x, -20.f), 20.f);
    float e = __expf(-2.f * xc);
    return (1.f - e) / (1.f + e);
}

// ---------------- embedding gather ----------------
__global__ void __launch_bounds__(256) embed_kernel(
    const int* __restrict__ ids, const float* __restrict__ tab, float* __restrict__ X) {
    int i = blockIdx.x * 256 + threadIdx.x;
    int q = i & 255, row = i >> 8;
    int b = row & 15, t = row >> 4;
    int id = ids[b * T_SEQ + t];
    reinterpret_cast<float4*>(X)[(size_t)row * 256 + q] =
        reinterpret_cast<const float4*>(tab)[(size_t)id * 256 + q];
}

// ---------------- pipelined TF32 GEMM (layer-0 input preactivations) ----------------
#define GA_STRIDE 20
#define GB_STRIDE 136
#define GA_TILE (128 * GA_STRIDE)
#define GB_TILE (16 * GB_STRIDE)
#define GEMM_SMEM_BYTES ((3 * GA_TILE + 3 * GB_TILE) * 4)

__global__ void __launch_bounds__(256) gemm_kernel(
    const float* __restrict__ A, const float* __restrict__ W,
    const float* __restrict__ bias, float* __restrict__ C, int K) {
    extern __shared__ __align__(16) float gsm[];
    float* As = gsm;
    float* Bs = gsm + 3 * GA_TILE;
    const int tid = threadIdx.x, lane = tid & 31, warp = tid >> 5;
    const int wm = warp >> 2, wn = warp & 3;
    const int gid = lane >> 2, tig = lane & 3;
    const int r0 = blockIdx.x * 128, n0 = blockIdx.y * 128;
    float acc[4][4][4] = {};

    const int ntiles = K >> 4;
    const int ar0 = tid >> 2, aq0 = (tid & 3) * 4;
    const int ar1 = (tid + 256) >> 2, aq1 = ((tid + 256) & 3) * 4;
    const int br0 = tid >> 5, bq0 = (tid & 31) * 4;
    const int br1 = (tid + 256) >> 5, bq1 = ((tid + 256) & 31) * 4;

#define COPY_TILE(s, kt)                                                                     \
    do {                                                                                     \
        int k0_ = (kt) << 4;                                                                 \
        cpasync16(As + (s) * GA_TILE + ar0 * GA_STRIDE + aq0,                                \
                  A + (size_t)(r0 + ar0) * K + k0_ + aq0);                                   \
        cpasync16(As + (s) * GA_TILE + ar1 * GA_STRIDE + aq1,                                \
                  A + (size_t)(r0 + ar1) * K + k0_ + aq1);                                   \
        cpasync16(Bs + (s) * GB_TILE + br0 * GB_STRIDE + bq0,                                \
                  W + (size_t)(k0_ + br0) * 2048 + n0 + bq0);                                \
        cpasync16(Bs + (s) * GB_TILE + br1 * GB_STRIDE + bq1,                                \
                  W + (size_t)(k0_ + br1) * 2048 + n0 + bq1);                                \
    } while (0)

    COPY_TILE(0, 0); cp_commit();
    COPY_TILE(1, 1); cp_commit();
    COPY_TILE(2, 2); cp_commit();

    for (int t = 0; t < ntiles; ++t) {
        int s = t % 3;
        const float* Asb = As + s * GA_TILE;
        const float* Bsb = Bs + s * GB_TILE;
        cp_wait2();
        __syncthreads();
#pragma unroll
        for (int kk = 0; kk < 16; kk += 8) {
            unsigned a[4][4], bb[4][2];
#pragma unroll
            for (int mt = 0; mt < 4; ++mt) {
                int m = wm * 64 + mt * 16;
                a[mt][0] = FT(Asb[(m + gid) * GA_STRIDE + kk + tig]);
                a[mt][1] = FT(Asb[(m + gid + 8) * GA_STRIDE + kk + tig]);
                a[mt][2] = FT(Asb[(m + gid) * GA_STRIDE + kk + tig + 4]);
                a[mt][3] = FT(Asb[(m + gid + 8) * GA_STRIDE + kk + tig + 4]);
            }
#pragma unroll
            for (int nt = 0; nt < 4; ++nt) {
                int nb = wn * 32 + nt * 8 + gid;
                bb[nt][0] = FT(Bsb[(kk + tig) * GB_STRIDE + nb]);
                bb[nt][1] = FT(Bsb[(kk + tig + 4) * GB_STRIDE + nb]);
            }
#pragma unroll
            for (int mt = 0; mt < 4; ++mt)
#pragma unroll
                for (int nt = 0; nt < 4; ++nt)
                    mma8(acc[mt][nt], a[mt], bb[nt]);
        }
        __syncthreads();
        if (t + 3 < ntiles) COPY_TILE(s, t + 3);
        cp_commit();
    }
#undef COPY_TILE

#pragma unroll
    for (int mt = 0; mt < 4; ++mt) {
#pragma unroll
        for (int nt = 0; nt < 4; ++nt) {
#pragma unroll
            for (int e = 0; e < 4; ++e) {
                int row = r0 + wm * 64 + mt * 16 + gid + ((e >> 1) * 8);
                int col = n0 + wn * 32 + nt * 8 + 2 * tig + (e & 1);
                float v = acc[mt][nt][e] + bias[col];
                int tt = row >> 4, b = row & 15;
                int gt = col >> 9, u = col & 511;
                size_t addr = (((size_t)tt * 32 + (u >> 4)) * 64 + gt * 16 + (u & 15)) * 16 + b;
                C[addr] = v;
            }
        }
    }
}

// ---------------- zero exchange/barrier state ----------------
__global__ void __launch_bounds__(256) zero_kernel() {
    int i = blockIdx.x * 256 + threadIdx.x;
    if (i < 16384) ((unsigned*)g_h0)[i] = 0u;
    if (i < 16384) ((unsigned*)g_h1)[i] = 0u;
    if (i < 2) g_cnt[i] = 0u;
}

// ---------------- fused layer-pipelined persistent scan ----------------
// 128 blocks: dir = bid>>6, role = (bid>>5)&1 (0 = layer0, 1 = layer1), blk = bid&31.
// Step s: L0 computes h0[s] (s<T); L1 computes h1[s-1] (s>=1) from h0[s-1], h1[s-2].
// L0: gates = Wh0slice^T @ h0_prev + Xp(t).  K=512, NKS=16 per kh-warp.
// L1: gates = [Wx1|Wh1]slice^T @ [h0|h1] + bias1.  K=1024, kh=0 -> x-part, kh=1 -> h-part.
#define FS_SMEM_BYTES (131072 + 2 * 16640 + 8704)

__global__ void __launch_bounds__(256, 1) fused_scan(
    const float* __restrict__ fW0, const float* __restrict__ fW1,
    const float* __restrict__ bW0, const float* __restrict__ bW1,
    const float* __restrict__ fb1, const float* __restrict__ bb1,
    const float* __restrict__ XpF, const float* __restrict__ XpB,
    float* __restrict__ out) {
    extern __shared__ __align__(16) char smraw[];
    unsigned* Wa = (unsigned*)smraw;                       // up to 32768 half2
    __half* hs0 = (__half*)(smraw + 131072);               // [16][520]
    __half* hs1 = (__half*)(smraw + 131072 + 16640);       // [16][520]
    float* Gb = (float*)(smraw + 131072 + 2 * 16640);      // [2][64][17]

    const int bid = blockIdx.x;
    const int dir = bid >> 6;
    const int role = (bid >> 5) & 1;
    const int blk = bid & 31;
    const int u0 = blk * 16;

    const int NKS = role ? 32 : 16;
    const int k_base = role ? 0 : 1024;
    const float* Wsrc = role ? (dir ? bW1 : fW1) : (dir ? bW0 : fW0);
    const float* Xp = dir ? XpB : XpF;

    const int tid = threadIdx.x, lane = tid & 31, warp = tid >> 5;
    const int mt = warp >> 1, kh = warp & 1;
    const int gid = lane >> 2, tig = lane & 3;

    // Weight slice -> fp16 fragment-major smem (one-time)
    const int total = 1024 * NKS;
    for (int idx = tid; idx < total; idx += 256) {
        int reg = idx & 3;
        int ln = (idx >> 2) & 31;
        int rest = idx >> 7;
        int ks = rest % NKS;
        int rest2 = rest / NKS;
        int khh = rest2 & 1;
        int mtt = rest2 >> 1;
        int lgid = ln >> 2, ltig = ln & 3;
        int m = mtt * 16 + ((reg & 1) << 3) + lgid;
        int k = k_base + (khh * NKS + ks) * 16 + ((reg >> 1) << 3) + 2 * ltig;
        int col = ((m >> 4) << 9) + u0 + (m & 15);
        __half2 v = __floats2half2_rn(Wsrc[(size_t)k * 2048 + col],
                                      Wsrc[(size_t)(k + 1) * 2048 + col]);
        Wa[idx] = *(unsigned*)&v;
    }
    __syncthreads();

    const int ej = tid & 15, eb = tid >> 4;
    const int q = tid & 63;
    const int b0_ = tid >> 6;

    // layer-1 bias registers
    float bi = 0.f, bg = 0.f, bf = 0.f, bo = 0.f;
    if (role) {
        const float* bias = dir ? bb1 : fb1;
        bi = bias[0 * 512 + u0 + ej];
        bg = bias[1 * 512 + u0 + ej];
        bf = bias[2 * 512 + u0 + ej];
        bo = bias[3 * 512 + u0 + ej];
    }

    float c_state = 0.f;
    unsigned* bar = &g_cnt[dir];
    const unsigned* Afb = Wa + ((mt * 2 + kh) * NKS) * 128 + lane * 4;
    float* Gp = Gb + kh * 1088;
    const __half* hb = (role && kh) ? hs1 : hs0;    // warp's B-operand buffer

    for (int s = 0; s <= T_SEQ; ++s) {
        const bool active = role ? (s >= 1) : (s < T_SEQ);
        if (active) {
            float xi = 0.f, xg = 0.f, xf = 0.f, xo = 0.f;
            if (!role) {
                int t = dir ? (T_SEQ - 1 - s) : s;
                const float* xp = Xp + ((size_t)t * 32 + blk) * 1024;
                xi = xp[(0 * 16 + ej) * 16 + eb];
                xg = xp[(1 * 16 + ej) * 16 + eb];
                xf = xp[(2 * 16 + ej) * 16 + eb];
                xo = xp[(3 * 16 + ej) * 16 + eb];
            }

            // stage h0 (and h1 for role1)
            const uint4* h0src = (const uint4*)g_h0[dir][s & 1];
#pragma unroll
            for (int i = 0; i < 4; ++i) {
                int b = b0_ + i * 4;
                *(uint4*)(hs0 + b * 520 + q * 8) = h0src[b * 64 + q];
            }
            if (role) {
                const uint4* h1src = (const uint4*)g_h1[dir][s & 1];
#pragma unroll
                for (int i = 0; i < 4; ++i) {
                    int b = b0_ + i * 4;
                    *(uint4*)(hs1 + b * 520 + q * 8) = h1src[b * 64 + q];
                }
            }
            __syncthreads();

            // gate GEMM (fp16, fp32 accum)
            float c0[4] = {}, c1[4] = {};
            const int k0b = role ? 0 : kh * 256;
            for (int ks = 0; ks < NKS; ++ks) {
                uint4 av = *(const uint4*)(Afb + ks * 128);
                unsigned a[4] = {av.x, av.y, av.z, av.w};
                int k0 = k0b + ks * 16;
                unsigned b00 = *(const unsigned*)(hb + gid * 520 + k0 + 2 * tig);
                unsigned b01 = *(const unsigned*)(hb + gid * 520 + k0 + 2 * tig + 8);
                unsigned b10 = *(const unsigned*)(hb + (8 + gid) * 520 + k0 + 2 * tig);
                unsigned b11 = *(const unsigned*)(hb + (8 + gid) * 520 + k0 + 2 * tig + 8);
                mma16h(c0, a, b00, b01);
                mma16h(c1, a, b10, b11);
            }

            int rb = mt * 16 + gid;
            Gp[rb * 17 + 2 * tig] = c0[0];
            Gp[rb * 17 + 2 * tig + 1] = c0[1];
            Gp[(rb + 8) * 17 + 2 * tig] = c0[2];
            Gp[(rb + 8) * 17 + 2 * tig + 1] = c0[3];
            Gp[rb * 17 + 8 + 2 * tig] = c1[0];
            Gp[rb * 17 + 8 + 2 * tig + 1] = c1[1];
            Gp[(rb + 8) * 17 + 8 + 2 * tig] = c1[2];
            Gp[(rb + 8) * 17 + 8 + 2 * tig + 1] = c1[3];
            __syncthreads();

            float gi = Gb[(0 * 16 + ej) * 17 + eb] + Gb[1088 + (0 * 16 + ej) * 17 + eb] + xi + bi;
            float gg = Gb[(1 * 16 + ej) * 17 + eb] + Gb[1088 + (1 * 16 + ej) * 17 + eb] + xg + bg;
            float gf = Gb[(2 * 16 + ej) * 17 + eb] + Gb[1088 + (2 * 16 + ej) * 17 + eb] + xf + bf;
            float go = Gb[(3 * 16 + ej) * 17 + eb] + Gb[1088 + (3 * 16 + ej) * 17 + eb] + xo + bo;
            float fgate = sigm(gf + 1.0f);
            c_state = fgate * c_state + sigm(gi) * tanh_(gg);
            float h = sigm(go) * tanh_(c_state);

            if (!role) {
                g_h0[dir][(s + 1) & 1][eb * 512 + u0 + ej] = __float2half(h);
            } else {
                g_h1[dir][(s + 1) & 1][eb * 512 + u0 + ej] = __float2half(h);
                int t1 = dir ? (T_SEQ - s) : (s - 1);
                out[((size_t)eb * 2048 + t1) * 1024 + dir * 512 + u0 + ej] = h;
            }
        }

        // inter-block barrier (64 blocks per direction)
        __threadfence();
        __syncthreads();
        if (tid == 0) {
            atomicAdd(bar, 1u);
            unsigned tgt = 64u * (unsigned)(s + 1);
            volatile unsigned* p = bar;
            while (*p < tgt) {}
        }
        __syncthreads();
        __threadfence();
    }
}

// ---------------- launch ----------------
extern "C" void kernel_launch(void* const* d_in, const int* in_sizes, int n_in,
                              void* d_out, int out_size) {
    const int* ids = (const int*)d_in[0];
    const float* tab = (const float*)d_in[1];
    const float* fW0 = (const float*)d_in[2];
    const float* fb0 = (const float*)d_in[3];
    const float* fW1 = (const float*)d_in[4];
    const float* fb1 = (const float*)d_in[5];
    const float* bW0 = (const float*)d_in[6];
    const float* bb0 = (const float*)d_in[7];
    const float* bW1 = (const float*)d_in[8];
    const float* bb1 = (const float*)d_in[9];
    float* out = (float*)d_out;

    cudaFuncSetAttribute(fused_scan, cudaFuncAttributeMaxDynamicSharedMemorySize,
                         FS_SMEM_BYTES);
    cudaFuncSetAttribute(gemm_kernel, cudaFuncAttributeMaxDynamicSharedMemorySize,
                         GEMM_SMEM_BYTES);

    float *X, *XpF, *XpB;
    cudaGetSymbolAddress((void**)&X, g_X);
    cudaGetSymbolAddress((void**)&XpF, g_XpF);
    cudaGetSymbolAddress((void**)&XpB, g_XpB);

    embed_kernel<<<(T_SEQ * NBATCH * 256) / 256, 256>>>(ids, tab, X);

    dim3 gg(256, 16);
    gemm_kernel<<<gg, 256, GEMM_SMEM_BYTES>>>(X, fW0, fb0, XpF, 1024);
    gemm_kernel<<<gg, 256, GEMM_SMEM_BYTES>>>(X, bW0, bb0, XpB, 1024);
    zero_kernel<<<128, 256>>>();
    fused_scan<<<128, 256, FS_SMEM_BYTES>>>(fW0, fW1, bW0, bW1, fb1, bb1,
                                            XpF, XpB, out);
}

// round 9
// speedup vs baseline: 3.2779x; 1.1168x over previous
#include <cuda_runtime.h>
#include <cuda_fp16.h>
#include <cuda_bf16.h>

#define T_SEQ 2048
#define NBATCH 16
#define DM 1024
#define HH 512

// ---------------- device scratch ----------------
__device__ float g_X[(size_t)T_SEQ * NBATCH * DM];
__device__ float g_XpF[(size_t)T_SEQ * NBATCH * 2048];
__device__ float g_XpB[(size_t)T_SEQ * NBATCH * 2048];
__device__ __half g_h0[2][2][NBATCH * HH];
__device__ __half g_h1[2][2][NBATCH * HH];
__device__ unsigned g_cnt[2];

// ---------------- helpers ----------------
__device__ __forceinline__ unsigned FT(float x) {
    unsigned u;
    asm("cvt.rna.tf32.f32 %0, %1;" : "=r"(u) : "f"(x));
    return u;
}

__device__ __forceinline__ void mma8(float c[4], const unsigned a[4], const unsigned b[2]) {
    asm volatile(
        "mma.sync.aligned.m16n8k8.row.col.f32.tf32.tf32.f32 "
        "{%0,%1,%2,%3},{%4,%5,%6,%7},{%8,%9},{%0,%1,%2,%3};"
        : "+f"(c[0]), "+f"(c[1]), "+f"(c[2]), "+f"(c[3])
        : "r"(a[0]), "r"(a[1]), "r"(a[2]), "r"(a[3]), "r"(b[0]), "r"(b[1]));
}

__device__ __forceinline__ void mma16h(float c[4], uint4 a, unsigned b0, unsigned b1) {
    asm volatile(
        "mma.sync.aligned.m16n8k16.row.col.f32.f16.f16.f32 "
        "{%0,%1,%2,%3},{%4,%5,%6,%7},{%8,%9},{%0,%1,%2,%3};"
        : "+f"(c[0]), "+f"(c[1]), "+f"(c[2]), "+f"(c[3])
        : "r"(a.x), "r"(a.y), "r"(a.z), "r"(a.w), "r"(b0), "r"(b1));
}

__device__ __forceinline__ void cpasync16(void* s, const void* g) {
    unsigned ss = (unsigned)__cvta_generic_to_shared(s);
    asm volatile("cp.async.ca.shared.global [%0], [%1], 16;" :: "r"(ss), "l"(g));
}
__device__ __forceinline__ void cp_commit() { asm volatile("cp.async.commit_group;"); }
__device__ __forceinline__ void cp_wait2() { asm volatile("cp.async.wait_group 2;"); }

__device__ __forceinline__ float sigm(float x) { return 1.f / (1.f + __expf(-x)); }
__device__ __forceinline__ float tanh_(float x) {
    float xc = fminf(fmaxf(x, -20.f), 20.f);
    float e = __expf(-2.f * xc);
    return (1.f - e) / (1.f + e);
}

// ---------------- embedding gather ----------------
__global__ void __launch_bounds__(256) embed_kernel(
    const int* __restrict__ ids, const float* __restrict__ tab, float* __restrict__ X) {
    int i = blockIdx.x * 256 + threadIdx.x;
    int q = i & 255, row = i >> 8;
    int b = row & 15, t = row >> 4;
    int id = ids[b * T_SEQ + t];
    reinterpret_cast<float4*>(X)[(size_t)row * 256 + q] =
        reinterpret_cast<const float4*>(tab)[(size_t)id * 256 + q];
}

// ---------------- pipelined TF32 GEMM (layer-0 input preactivations) ----------------
#define GA_STRIDE 20
#define GB_STRIDE 136
#define GA_TILE (128 * GA_STRIDE)
#define GB_TILE (16 * GB_STRIDE)
#define GEMM_SMEM_BYTES ((3 * GA_TILE + 3 * GB_TILE) * 4)

__global__ void __launch_bounds__(256) gemm_kernel(
    const float* __restrict__ A, const float* __restrict__ W,
    const float* __restrict__ bias, float* __restrict__ C, int K) {
    extern __shared__ __align__(16) float gsm[];
    float* As = gsm;
    float* Bs = gsm + 3 * GA_TILE;
    const int tid = threadIdx.x, lane = tid & 31, warp = tid >> 5;
    const int wm = warp >> 2, wn = warp & 3;
    const int gid = lane >> 2, tig = lane & 3;
    const int r0 = blockIdx.x * 128, n0 = blockIdx.y * 128;
    float acc[4][4][4] = {};

    const int ntiles = K >> 4;
    const int ar0 = tid >> 2, aq0 = (tid & 3) * 4;
    const int ar1 = (tid + 256) >> 2, aq1 = ((tid + 256) & 3) * 4;
    const int br0 = tid >> 5, bq0 = (tid & 31) * 4;
    const int br1 = (tid + 256) >> 5, bq1 = ((tid + 256) & 31) * 4;

#define COPY_TILE(s, kt)                                                                     \
    do {                                                                                     \
        int k0_ = (kt) << 4;                                                                 \
        cpasync16(As + (s) * GA_TILE + ar0 * GA_STRIDE + aq0,                                \
                  A + (size_t)(r0 + ar0) * K + k0_ + aq0);                                   \
        cpasync16(As + (s) * GA_TILE + ar1 * GA_STRIDE + aq1,                                \
                  A + (size_t)(r0 + ar1) * K + k0_ + aq1);                                   \
        cpasync16(Bs + (s) * GB_TILE + br0 * GB_STRIDE + bq0,                                \
                  W + (size_t)(k0_ + br0) * 2048 + n0 + bq0);                                \
        cpasync16(Bs + (s) * GB_TILE + br1 * GB_STRIDE + bq1,                                \
                  W + (size_t)(k0_ + br1) * 2048 + n0 + bq1);                                \
    } while (0)

    COPY_TILE(0, 0); cp_commit();
    COPY_TILE(1, 1); cp_commit();
    COPY_TILE(2, 2); cp_commit();

    for (int t = 0; t < ntiles; ++t) {
        int s = t % 3;
        const float* Asb = As + s * GA_TILE;
        const float* Bsb = Bs + s * GB_TILE;
        cp_wait2();
        __syncthreads();
#pragma unroll
        for (int kk = 0; kk < 16; kk += 8) {
            unsigned a[4][4], bb[4][2];
#pragma unroll
            for (int mt = 0; mt < 4; ++mt) {
                int m = wm * 64 + mt * 16;
                a[mt][0] = FT(Asb[(m + gid) * GA_STRIDE + kk + tig]);
                a[mt][1] = FT(Asb[(m + gid + 8) * GA_STRIDE + kk + tig]);
                a[mt][2] = FT(Asb[(m + gid) * GA_STRIDE + kk + tig + 4]);
                a[mt][3] = FT(Asb[(m + gid + 8) * GA_STRIDE + kk + tig + 4]);
            }
#pragma unroll
            for (int nt = 0; nt < 4; ++nt) {
                int nb = wn * 32 + nt * 8 + gid;
                bb[nt][0] = FT(Bsb[(kk + tig) * GB_STRIDE + nb]);
                bb[nt][1] = FT(Bsb[(kk + tig + 4) * GB_STRIDE + nb]);
            }
#pragma unroll
            for (int mt = 0; mt < 4; ++mt)
#pragma unroll
                for (int nt = 0; nt < 4; ++nt)
                    mma8(acc[mt][nt], a[mt], bb[nt]);
        }
        __syncthreads();
        if (t + 3 < ntiles) COPY_TILE(s, t + 3);
        cp_commit();
    }
#undef COPY_TILE

#pragma unroll
    for (int mt = 0; mt < 4; ++mt) {
#pragma unroll
        for (int nt = 0; nt < 4; ++nt) {
#pragma unroll
            for (int e = 0; e < 4; ++e) {
                int row = r0 + wm * 64 + mt * 16 + gid + ((e >> 1) * 8);
                int col = n0 + wn * 32 + nt * 8 + 2 * tig + (e & 1);
                float v = acc[mt][nt][e] + bias[col];
                int tt = row >> 4, b = row & 15;
                int gt = col >> 9, u = col & 511;
                size_t addr = (((size_t)tt * 32 + (u >> 4)) * 64 + gt * 16 + (u & 15)) * 16 + b;
                C[addr] = v;
            }
        }
    }
}

// ---------------- zero exchange/barrier state ----------------
__global__ void __launch_bounds__(256) zero_kernel() {
    int i = blockIdx.x * 256 + threadIdx.x;
    if (i < 16384) ((unsigned*)g_h0)[i] = 0u;
    if (i < 16384) ((unsigned*)g_h1)[i] = 0u;
    if (i < 2) g_cnt[i] = 0u;
}

// ---------------- fused layer-pipelined persistent scan ----------------
#define FS_SMEM_BYTES (131072 + 2 * 16640 + 8704)

// Time loop templated on ROLE so the static A-fragments live in registers.
template <int ROLE>
__device__ __forceinline__ void scan_loop(
    const unsigned* __restrict__ Wa, __half* hs0, __half* hs1, float* Gb,
    const float* __restrict__ Xp, float* __restrict__ out,
    unsigned* bar, int dir, int blk, int u0,
    float bi, float bg, float bf, float bo) {
    constexpr int NKS = ROLE ? 32 : 16;

    const int tid = threadIdx.x, lane = tid & 31, warp = tid >> 5;
    const int mt = warp >> 1, kh = warp & 1;
    const int gid = lane >> 2, tig = lane & 3;
    const int ej = tid & 15, eb = tid >> 4;
    const int q = tid & 63;
    const int b0_ = tid >> 6;

    // preload static A fragments into registers (loop-invariant across all steps)
    const unsigned* Afb = Wa + ((mt * 2 + kh) * NKS) * 128 + lane * 4;
    uint4 Areg[NKS];
#pragma unroll
    for (int ks = 0; ks < NKS; ++ks) Areg[ks] = *(const uint4*)(Afb + ks * 128);

    float c_state = 0.f;
    float* Gp = Gb + kh * 1088;
    const __half* hb = (ROLE && kh) ? hs1 : hs0;

    for (int s = 0; s <= T_SEQ; ++s) {
        const bool active = ROLE ? (s >= 1) : (s < T_SEQ);
        if (active) {
            float xi = 0.f, xg = 0.f, xf = 0.f, xo = 0.f;
            if (!ROLE) {
                int t = dir ? (T_SEQ - 1 - s) : s;
                const float* xp = Xp + ((size_t)t * 32 + blk) * 1024;
                xi = xp[(0 * 16 + ej) * 16 + eb];
                xg = xp[(1 * 16 + ej) * 16 + eb];
                xf = xp[(2 * 16 + ej) * 16 + eb];
                xo = xp[(3 * 16 + ej) * 16 + eb];
            }

            const uint4* h0src = (const uint4*)g_h0[dir][s & 1];
#pragma unroll
            for (int i = 0; i < 4; ++i) {
                int b = b0_ + i * 4;
                *(uint4*)(hs0 + b * 520 + q * 8) = h0src[b * 64 + q];
            }
            if (ROLE) {
                const uint4* h1src = (const uint4*)g_h1[dir][s & 1];
#pragma unroll
                for (int i = 0; i < 4; ++i) {
                    int b = b0_ + i * 4;
                    *(uint4*)(hs1 + b * 520 + q * 8) = h1src[b * 64 + q];
                }
            }
            __syncthreads();

            float c0[4] = {}, c1[4] = {};
            const int k0b = ROLE ? 0 : kh * 256;
#pragma unroll
            for (int ks = 0; ks < NKS; ++ks) {
                int k0 = k0b + ks * 16;
                unsigned b00 = *(const unsigned*)(hb + gid * 520 + k0 + 2 * tig);
                unsigned b01 = *(const unsigned*)(hb + gid * 520 + k0 + 2 * tig + 8);
                unsigned b10 = *(const unsigned*)(hb + (8 + gid) * 520 + k0 + 2 * tig);
                unsigned b11 = *(const unsigned*)(hb + (8 + gid) * 520 + k0 + 2 * tig + 8);
                mma16h(c0, Areg[ks], b00, b01);
                mma16h(c1, Areg[ks], b10, b11);
            }

            int rb = mt * 16 + gid;
            Gp[rb * 17 + 2 * tig] = c0[0];
            Gp[rb * 17 + 2 * tig + 1] = c0[1];
            Gp[(rb + 8) * 17 + 2 * tig] = c0[2];
            Gp[(rb + 8) * 17 + 2 * tig + 1] = c0[3];
            Gp[rb * 17 + 8 + 2 * tig] = c1[0];
            Gp[rb * 17 + 8 + 2 * tig + 1] = c1[1];
            Gp[(rb + 8) * 17 + 8 + 2 * tig] = c1[2];
            Gp[(rb + 8) * 17 + 8 + 2 * tig + 1] = c1[3];
            __syncthreads();

            float gi = Gb[(0 * 16 + ej) * 17 + eb] + Gb[1088 + (0 * 16 + ej) * 17 + eb] + xi + bi;
            float gg = Gb[(1 * 16 + ej) * 17 + eb] + Gb[1088 + (1 * 16 + ej) * 17 + eb] + xg + bg;
            float gf = Gb[(2 * 16 + ej) * 17 + eb] + Gb[1088 + (2 * 16 + ej) * 17 + eb] + xf + bf;
            float go = Gb[(3 * 16 + ej) * 17 + eb] + Gb[1088 + (3 * 16 + ej) * 17 + eb] + xo + bo;
            float fgate = sigm(gf + 1.0f);
            c_state = fgate * c_state + sigm(gi) * tanh_(gg);
            float h = sigm(go) * tanh_(c_state);

            if (!ROLE) {
                g_h0[dir][(s + 1) & 1][eb * 512 + u0 + ej] = __float2half(h);
            } else {
                g_h1[dir][(s + 1) & 1][eb * 512 + u0 + ej] = __float2half(h);
                int t1 = dir ? (T_SEQ - s) : (s - 1);
                out[((size_t)eb * 2048 + t1) * 1024 + dir * 512 + u0 + ej] = h;
            }
        }

        __threadfence();
        __syncthreads();
        if (tid == 0) {
            atomicAdd(bar, 1u);
            unsigned tgt = 64u * (unsigned)(s + 1);
            volatile unsigned* p = bar;
            while (*p < tgt) {}
        }
        __syncthreads();
        __threadfence();
    }
}

__global__ void __launch_bounds__(256, 1) fused_scan(
    const float* __restrict__ fW0, const float* __restrict__ fW1,
    const float* __restrict__ bW0, const float* __restrict__ bW1,
    const float* __restrict__ fb1, const float* __restrict__ bb1,
    const float* __restrict__ XpF, const float* __restrict__ XpB,
    float* __restrict__ out) {
    extern __shared__ __align__(16) char smraw[];
    unsigned* Wa = (unsigned*)smraw;
    __half* hs0 = (__half*)(smraw + 131072);
    __half* hs1 = (__half*)(smraw + 131072 + 16640);
    float* Gb = (float*)(smraw + 131072 + 2 * 16640);

    const int bid = blockIdx.x;
    const int dir = bid >> 6;
    const int role = (bid >> 5) & 1;
    const int blk = bid & 31;
    const int u0 = blk * 16;

    const int NKS = role ? 32 : 16;
    const int k_base = role ? 0 : 1024;
    const float* Wsrc = role ? (dir ? bW1 : fW1) : (dir ? bW0 : fW0);
    const float* Xp = dir ? XpB : XpF;

    const int tid = threadIdx.x;

    // Weight slice -> fp16 fragment-major smem (one-time staging)
    const int total = 1024 * NKS;
    for (int idx = tid; idx < total; idx += 256) {
        int reg = idx & 3;
        int ln = (idx >> 2) & 31;
        int rest = idx >> 7;
        int ks = rest % NKS;
        int rest2 = rest / NKS;
        int khh = rest2 & 1;
        int mtt = rest2 >> 1;
        int lgid = ln >> 2, ltig = ln & 3;
        int m = mtt * 16 + ((reg & 1) << 3) + lgid;
        int k = k_base + (khh * NKS + ks) * 16 + ((reg >> 1) << 3) + 2 * ltig;
        int col = ((m >> 4) << 9) + u0 + (m & 15);
        __half2 v = __floats2half2_rn(Wsrc[(size_t)k * 2048 + col],
                                      Wsrc[(size_t)(k + 1) * 2048 + col]);
        Wa[idx] = *(unsigned*)&v;
    }
    __syncthreads();

    float bi = 0.f, bg = 0.f, bf = 0.f, bo = 0.f;
    if (role) {
        const float* bias = dir ? bb1 : fb1;
        int ej = tid & 15;
        bi = bias[0 * 512 + u0 + ej];
        bg = bias[1 * 512 + u0 + ej];
        bf = bias[2 * 512 + u0 + ej];
        bo = bias[3 * 512 + u0 + ej];
    }

    unsigned* bar = &g_cnt[dir];
    if (role)
        scan_loop<1>(Wa, hs0, hs1, Gb, Xp, out, bar, dir, blk, u0, bi, bg, bf, bo);
    else
        scan_loop<0>(Wa, hs0, hs1, Gb, Xp, out, bar, dir, blk, u0, bi, bg, bf, bo);
}

// ---------------- launch ----------------
extern "C" void kernel_launch(void* const* d_in, const int* in_sizes, int n_in,
                              void* d_out, int out_size) {
    const int* ids = (const int*)d_in[0];
    const float* tab = (const float*)d_in[1];
    const float* fW0 = (const float*)d_in[2];
    const float* fb0 = (const float*)d_in[3];
    const float* fW1 = (const float*)d_in[4];
    const float* fb1 = (const float*)d_in[5];
    const float* bW0 = (const float*)d_in[6];
    const float* bb0 = (const float*)d_in[7];
    const float* bW1 = (const float*)d_in[8];
    const float* bb1 = (const float*)d_in[9];
    float* out = (float*)d_out;

    cudaFuncSetAttribute(fused_scan, cudaFuncAttributeMaxDynamicSharedMemorySize,
                         FS_SMEM_BYTES);
    cudaFuncSetAttribute(gemm_kernel, cudaFuncAttributeMaxDynamicSharedMemorySize,
                         GEMM_SMEM_BYTES);

    float *X, *XpF, *XpB;
    cudaGetSymbolAddress((void**)&X, g_X);
    cudaGetSymbolAddress((void**)&XpF, g_XpF);
    cudaGetSymbolAddress((void**)&XpB, g_XpB);

    embed_kernel<<<(T_SEQ * NBATCH * 256) / 256, 256>>>(ids, tab, X);

    dim3 gg(256, 16);
    gemm_kernel<<<gg, 256, GEMM_SMEM_BYTES>>>(X, fW0, fb0, XpF, 1024);
    gemm_kernel<<<gg, 256, GEMM_SMEM_BYTES>>>(X, bW0, bb0, XpB, 1024);
    zero_kernel<<<128, 256>>>();
    fused_scan<<<128, 256, FS_SMEM_BYTES>>>(fW0, fW1, bW0, bW1, fb1, bb1,
                                            XpF, XpB, out);
}

// round 10
// speedup vs baseline: 3.6507x; 1.1137x over previous
#include <cuda_runtime.h>
#include <cuda_fp16.h>
#include <cuda_bf16.h>

#define T_SEQ 2048
#define NBATCH 16
#define DM 1024
#define HH 512

// ---------------- device scratch ----------------
__device__ __half g_Xh[(size_t)T_SEQ * NBATCH * DM];        // fp16 embedded inputs
__device__ __half g_Wt[2][(size_t)2048 * DM];               // fp16 W0^T [dir][n*1024+k]
__device__ float g_XpF[(size_t)T_SEQ * NBATCH * 2048];
__device__ float g_XpB[(size_t)T_SEQ * NBATCH * 2048];
__device__ __half g_h0[2][2][NBATCH * HH];
__device__ __half g_h1[2][2][NBATCH * HH];
__device__ unsigned g_cnt[2];

// ---------------- helpers ----------------
__device__ __forceinline__ void mma16h(float c[4], uint4 a, unsigned b0, unsigned b1) {
    asm volatile(
        "mma.sync.aligned.m16n8k16.row.col.f32.f16.f16.f32 "
        "{%0,%1,%2,%3},{%4,%5,%6,%7},{%8,%9},{%0,%1,%2,%3};"
        : "+f"(c[0]), "+f"(c[1]), "+f"(c[2]), "+f"(c[3])
        : "r"(a.x), "r"(a.y), "r"(a.z), "r"(a.w), "r"(b0), "r"(b1));
}

__device__ __forceinline__ void cpasync16(void* s, const void* g) {
    unsigned ss = (unsigned)__cvta_generic_to_shared(s);
    asm volatile("cp.async.ca.shared.global [%0], [%1], 16;" :: "r"(ss), "l"(g));
}
__device__ __forceinline__ void cp_commit() { asm volatile("cp.async.commit_group;"); }
__device__ __forceinline__ void cp_wait2() { asm volatile("cp.async.wait_group 2;"); }

__device__ __forceinline__ float sigm(float x) { return 1.f / (1.f + __expf(-x)); }
__device__ __forceinline__ float tanh_(float x) {
    float xc = fminf(fmaxf(x, -20.f), 20.f);
    float e = __expf(-2.f * xc);
    return (1.f - e) / (1.f + e);
}

// ---------------- embedding gather (fp16 output) ----------------
__global__ void __launch_bounds__(256) embed_kernel(
    const int* __restrict__ ids, const float* __restrict__ tab, __half* __restrict__ Xh) {
    int i = blockIdx.x * 256 + threadIdx.x;      // over T*B*128 8-half groups
    int q = i & 127, row = i >> 7;
    int b = row & 15, t = row >> 4;
    int id = ids[b * T_SEQ + t];
    const float4* src = reinterpret_cast<const float4*>(tab) + (size_t)id * 256 + q * 2;
    float4 v0 = src[0], v1 = src[1];
    __half2 h0 = __floats2half2_rn(v0.x, v0.y);
    __half2 h1 = __floats2half2_rn(v0.z, v0.w);
    __half2 h2 = __floats2half2_rn(v1.x, v1.y);
    __half2 h3 = __floats2half2_rn(v1.z, v1.w);
    uint4 out;
    out.x = *(unsigned*)&h0; out.y = *(unsigned*)&h1;
    out.z = *(unsigned*)&h2; out.w = *(unsigned*)&h3;
    reinterpret_cast<uint4*>(Xh)[(size_t)row * 128 + q] = out;
}

// ---------------- W0 -> fp16 transposed [n][k] ----------------
__global__ void __launch_bounds__(256) wconv_kernel(
    const float* __restrict__ fW0, const float* __restrict__ bW0) {
    int idx = blockIdx.x * 256 + threadIdx.x;    // 2 * 2048 * 1024
    int n = idx & 2047;
    int k = (idx >> 11) & 1023;
    int d = idx >> 21;
    const float* src = d ? bW0 : fW0;
    g_Wt[d][(size_t)n * 1024 + k] = __float2half(src[(size_t)k * 2048 + n]);
}

// ---------------- pipelined FP16 GEMM (layer-0 input preactivations) ----------------
// Xp[perm] = Xh[M,1024] @ W[1024,2048] + bias, via Wt[n][k]. Tile 128x128, BK=32.
#define HA_STRIDE 40
#define HA_TILE (128 * HA_STRIDE)                 // halves per stage per operand
#define GEMMH_SMEM_BYTES (6 * HA_TILE * 2)        // 3 stages x (A + B)

__global__ void __launch_bounds__(256) gemmh_kernel(
    const __half* __restrict__ Xh, const __half* __restrict__ Wt,
    const float* __restrict__ bias, float* __restrict__ C) {
    extern __shared__ __align__(16) __half hsm[];
    __half* Ah = hsm;                             // [3][128][40]
    __half* Bh = hsm + 3 * HA_TILE;               // [3][128][40]
    const int tid = threadIdx.x, lane = tid & 31, warp = tid >> 5;
    const int wm = warp >> 2, wn = warp & 3;
    const int gid = lane >> 2, tig = lane & 3;
    const int r0 = blockIdx.x * 128, n0 = blockIdx.y * 128;
    float acc[4][4][4] = {};

    const int c0r = tid >> 2, c0q = (tid & 3) * 8;
    const int c1r = (tid + 256) >> 2, c1q = ((tid + 256) & 3) * 8;

#define COPY_H(s, kt)                                                                      \
    do {                                                                                   \
        int k0_ = (kt) << 5;                                                               \
        cpasync16(Ah + (s) * HA_TILE + c0r * HA_STRIDE + c0q,                              \
                  Xh + (size_t)(r0 + c0r) * 1024 + k0_ + c0q);                             \
        cpasync16(Ah + (s) * HA_TILE + c1r * HA_STRIDE + c1q,                              \
                  Xh + (size_t)(r0 + c1r) * 1024 + k0_ + c1q);                             \
        cpasync16(Bh + (s) * HA_TILE + c0r * HA_STRIDE + c0q,                              \
                  Wt + (size_t)(n0 + c0r) * 1024 + k0_ + c0q);                             \
        cpasync16(Bh + (s) * HA_TILE + c1r * HA_STRIDE + c1q,                              \
                  Wt + (size_t)(n0 + c1r) * 1024 + k0_ + c1q);                             \
    } while (0)

    COPY_H(0, 0); cp_commit();
    COPY_H(1, 1); cp_commit();
    COPY_H(2, 2); cp_commit();

    for (int t = 0; t < 32; ++t) {
        int s = t % 3;
        const __half* Asb = Ah + s * HA_TILE;
        const __half* Bsb = Bh + s * HA_TILE;
        cp_wait2();
        __syncthreads();
#pragma unroll
        for (int kk = 0; kk < 32; kk += 16) {
            uint4 a[4];
            unsigned bb[4][2];
#pragma unroll
            for (int mt = 0; mt < 4; ++mt) {
                int m = wm * 64 + mt * 16;
                a[mt].x = *(const unsigned*)(Asb + (m + gid) * HA_STRIDE + kk + 2 * tig);
                a[mt].y = *(const unsigned*)(Asb + (m + gid + 8) * HA_STRIDE + kk + 2 * tig);
                a[mt].z = *(const unsigned*)(Asb + (m + gid) * HA_STRIDE + kk + 2 * tig + 8);
                a[mt].w = *(const unsigned*)(Asb + (m + gid + 8) * HA_STRIDE + kk + 2 * tig + 8);
            }
#pragma unroll
            for (int nt = 0; nt < 4; ++nt) {
                int n = wn * 32 + nt * 8 + gid;
                bb[nt][0] = *(const unsigned*)(Bsb + n * HA_STRIDE + kk + 2 * tig);
                bb[nt][1] = *(const unsigned*)(Bsb + n * HA_STRIDE + kk + 2 * tig + 8);
            }
#pragma unroll
            for (int mt = 0; mt < 4; ++mt)
#pragma unroll
                for (int nt = 0; nt < 4; ++nt)
                    mma16h(acc[mt][nt], a[mt], bb[nt][0], bb[nt][1]);
        }
        __syncthreads();
        if (t + 3 < 32) COPY_H(s, t + 3);
        cp_commit();
    }
#undef COPY_H

#pragma unroll
    for (int mt = 0; mt < 4; ++mt) {
#pragma unroll
        for (int nt = 0; nt < 4; ++nt) {
#pragma unroll
            for (int e = 0; e < 4; ++e) {
                int row = r0 + wm * 64 + mt * 16 + gid + ((e >> 1) * 8);
                int col = n0 + wn * 32 + nt * 8 + 2 * tig + (e & 1);
                float v = acc[mt][nt][e] + bias[col];
                int tt = row >> 4, b = row & 15;
                int gt = col >> 9, u = col & 511;
                size_t addr = (((size_t)tt * 32 + (u >> 4)) * 64 + gt * 16 + (u & 15)) * 16 + b;
                C[addr] = v;
            }
        }
    }
}

// ---------------- zero exchange/barrier state ----------------
__global__ void __launch_bounds__(256) zero_kernel() {
    int i = blockIdx.x * 256 + threadIdx.x;
    if (i < 16384) ((unsigned*)g_h0)[i] = 0u;
    if (i < 16384) ((unsigned*)g_h1)[i] = 0u;
    if (i < 2) g_cnt[i] = 0u;
}

// ---------------- fused layer-pipelined persistent scan (unchanged from R9) ----------------
#define FS_SMEM_BYTES (131072 + 2 * 16640 + 8704)

template <int ROLE>
__device__ __forceinline__ void scan_loop(
    const unsigned* __restrict__ Wa, __half* hs0, __half* hs1, float* Gb,
    const float* __restrict__ Xp, float* __restrict__ out,
    unsigned* bar, int dir, int blk, int u0,
    float bi, float bg, float bf, float bo) {
    constexpr int NKS = ROLE ? 32 : 16;

    const int tid = threadIdx.x, lane = tid & 31, warp = tid >> 5;
    const int mt = warp >> 1, kh = warp & 1;
    const int gid = lane >> 2, tig = lane & 3;
    const int ej = tid & 15, eb = tid >> 4;
    const int q = tid & 63;
    const int b0_ = tid >> 6;

    const unsigned* Afb = Wa + ((mt * 2 + kh) * NKS) * 128 + lane * 4;
    uint4 Areg[NKS];
#pragma unroll
    for (int ks = 0; ks < NKS; ++ks) Areg[ks] = *(const uint4*)(Afb + ks * 128);

    float c_state = 0.f;
    float* Gp = Gb + kh * 1088;
    const __half* hb = (ROLE && kh) ? hs1 : hs0;

    for (int s = 0; s <= T_SEQ; ++s) {
        const bool active = ROLE ? (s >= 1) : (s < T_SEQ);
        if (active) {
            float xi = 0.f, xg = 0.f, xf = 0.f, xo = 0.f;
            if (!ROLE) {
                int t = dir ? (T_SEQ - 1 - s) : s;
                const float* xp = Xp + ((size_t)t * 32 + blk) * 1024;
                xi = xp[(0 * 16 + ej) * 16 + eb];
                xg = xp[(1 * 16 + ej) * 16 + eb];
                xf = xp[(2 * 16 + ej) * 16 + eb];
                xo = xp[(3 * 16 + ej) * 16 + eb];
            }

            const uint4* h0src = (const uint4*)g_h0[dir][s & 1];
#pragma unroll
            for (int i = 0; i < 4; ++i) {
                int b = b0_ + i * 4;
                *(uint4*)(hs0 + b * 520 + q * 8) = h0src[b * 64 + q];
            }
            if (ROLE) {
                const uint4* h1src = (const uint4*)g_h1[dir][s & 1];
#pragma unroll
                for (int i = 0; i < 4; ++i) {
                    int b = b0_ + i * 4;
                    *(uint4*)(hs1 + b * 520 + q * 8) = h1src[b * 64 + q];
                }
            }
            __syncthreads();

            float c0[4] = {}, c1[4] = {};
            const int k0b = ROLE ? 0 : kh * 256;
#pragma unroll
            for (int ks = 0; ks < NKS; ++ks) {
                int k0 = k0b + ks * 16;
                unsigned b00 = *(const unsigned*)(hb + gid * 520 + k0 + 2 * tig);
                unsigned b01 = *(const unsigned*)(hb + gid * 520 + k0 + 2 * tig + 8);
                unsigned b10 = *(const unsigned*)(hb + (8 + gid) * 520 + k0 + 2 * tig);
                unsigned b11 = *(const unsigned*)(hb + (8 + gid) * 520 + k0 + 2 * tig + 8);
                mma16h(c0, Areg[ks], b00, b01);
                mma16h(c1, Areg[ks], b10, b11);
            }

            int rb = mt * 16 + gid;
            Gp[rb * 17 + 2 * tig] = c0[0];
            Gp[rb * 17 + 2 * tig + 1] = c0[1];
            Gp[(rb + 8) * 17 + 2 * tig] = c0[2];
            Gp[(rb + 8) * 17 + 2 * tig + 1] = c0[3];
            Gp[rb * 17 + 8 + 2 * tig] = c1[0];
            Gp[rb * 17 + 8 + 2 * tig + 1] = c1[1];
            Gp[(rb + 8) * 17 + 8 + 2 * tig] = c1[2];
            Gp[(rb + 8) * 17 + 8 + 2 * tig + 1] = c1[3];
            __syncthreads();

            float gi = Gb[(0 * 16 + ej) * 17 + eb] + Gb[1088 + (0 * 16 + ej) * 17 + eb] + xi + bi;
            float gg = Gb[(1 * 16 + ej) * 17 + eb] + Gb[1088 + (1 * 16 + ej) * 17 + eb] + xg + bg;
            float gf = Gb[(2 * 16 + ej) * 17 + eb] + Gb[1088 + (2 * 16 + ej) * 17 + eb] + xf + bf;
            float go = Gb[(3 * 16 + ej) * 17 + eb] + Gb[1088 + (3 * 16 + ej) * 17 + eb] + xo + bo;
            float fgate = sigm(gf + 1.0f);
            c_state = fgate * c_state + sigm(gi) * tanh_(gg);
            float h = sigm(go) * tanh_(c_state);

            if (!ROLE) {
                g_h0[dir][(s + 1) & 1][eb * 512 + u0 + ej] = __float2half(h);
            } else {
                g_h1[dir][(s + 1) & 1][eb * 512 + u0 + ej] = __float2half(h);
                int t1 = dir ? (T_SEQ - s) : (s - 1);
                out[((size_t)eb * 2048 + t1) * 1024 + dir * 512 + u0 + ej] = h;
            }
        }

        __threadfence();
        __syncthreads();
        if (tid == 0) {
            atomicAdd(bar, 1u);
            unsigned tgt = 64u * (unsigned)(s + 1);
            volatile unsigned* p = bar;
            while (*p < tgt) {}
        }
        __syncthreads();
        __threadfence();
    }
}

__global__ void __launch_bounds__(256, 1) fused_scan(
    const float* __restrict__ fW0, const float* __restrict__ fW1,
    const float* __restrict__ bW0, const float* __restrict__ bW1,
    const float* __restrict__ fb1, const float* __restrict__ bb1,
    const float* __restrict__ XpF, const float* __restrict__ XpB,
    float* __restrict__ out) {
    extern __shared__ __align__(16) char smraw[];
    unsigned* Wa = (unsigned*)smraw;
    __half* hs0 = (__half*)(smraw + 131072);
    __half* hs1 = (__half*)(smraw + 131072 + 16640);
    float* Gb = (float*)(smraw + 131072 + 2 * 16640);

    const int bid = blockIdx.x;
    const int dir = bid >> 6;
    const int role = (bid >> 5) & 1;
    const int blk = bid & 31;
    const int u0 = blk * 16;

    const int NKS = role ? 32 : 16;
    const int k_base = role ? 0 : 1024;
    const float* Wsrc = role ? (dir ? bW1 : fW1) : (dir ? bW0 : fW0);
    const float* Xp = dir ? XpB : XpF;

    const int tid = threadIdx.x;

    const int total = 1024 * NKS;
    for (int idx = tid; idx < total; idx += 256) {
        int reg = idx & 3;
        int ln = (idx >> 2) & 31;
        int rest = idx >> 7;
        int ks = rest % NKS;
        int rest2 = rest / NKS;
        int khh = rest2 & 1;
        int mtt = rest2 >> 1;
        int lgid = ln >> 2, ltig = ln & 3;
        int m = mtt * 16 + ((reg & 1) << 3) + lgid;
        int k = k_base + (khh * NKS + ks) * 16 + ((reg >> 1) << 3) + 2 * ltig;
        int col = ((m >> 4) << 9) + u0 + (m & 15);
        __half2 v = __floats2half2_rn(Wsrc[(size_t)k * 2048 + col],
                                      Wsrc[(size_t)(k + 1) * 2048 + col]);
        Wa[idx] = *(unsigned*)&v;
    }
    __syncthreads();

    float bi = 0.f, bg = 0.f, bf = 0.f, bo = 0.f;
    if (role) {
        const float* bias = dir ? bb1 : fb1;
        int ej = tid & 15;
        bi = bias[0 * 512 + u0 + ej];
        bg = bias[1 * 512 + u0 + ej];
        bf = bias[2 * 512 + u0 + ej];
        bo = bias[3 * 512 + u0 + ej];
    }

    unsigned* bar = &g_cnt[dir];
    if (role)
        scan_loop<1>(Wa, hs0, hs1, Gb, Xp, out, bar, dir, blk, u0, bi, bg, bf, bo);
    else
        scan_loop<0>(Wa, hs0, hs1, Gb, Xp, out, bar, dir, blk, u0, bi, bg, bf, bo);
}

// ---------------- launch ----------------
extern "C" void kernel_launch(void* const* d_in, const int* in_sizes, int n_in,
                              void* d_out, int out_size) {
    const int* ids = (const int*)d_in[0];
    const float* tab = (const float*)d_in[1];
    const float* fW0 = (const float*)d_in[2];
    const float* fb0 = (const float*)d_in[3];
    const float* fW1 = (const float*)d_in[4];
    const float* fb1 = (const float*)d_in[5];
    const float* bW0 = (const float*)d_in[6];
    const float* bb0 = (const float*)d_in[7];
    const float* bW1 = (const float*)d_in[8];
    const float* bb1 = (const float*)d_in[9];
    float* out = (float*)d_out;

    cudaFuncSetAttribute(fused_scan, cudaFuncAttributeMaxDynamicSharedMemorySize,
                         FS_SMEM_BYTES);
    cudaFuncSetAttribute(gemmh_kernel, cudaFuncAttributeMaxDynamicSharedMemorySize,
                         GEMMH_SMEM_BYTES);

    __half *Xh, *Wt0, *Wt1;
    float *XpF, *XpB;
    cudaGetSymbolAddress((void**)&Xh, g_Xh);
    cudaGetSymbolAddress((void**)&Wt0, g_Wt);
    Wt1 = Wt0 + (size_t)2048 * 1024;
    cudaGetSymbolAddress((void**)&XpF, g_XpF);
    cudaGetSymbolAddress((void**)&XpB, g_XpB);

    embed_kernel<<<(T_SEQ * NBATCH * 128) / 256, 256>>>(ids, tab, Xh);
    wconv_kernel<<<(2 * 2048 * 1024) / 256, 256>>>(fW0, bW0);

    dim3 gg(256, 16);
    gemmh_kernel<<<gg, 256, GEMMH_SMEM_BYTES>>>(Xh, Wt0, fb0, XpF);
    gemmh_kernel<<<gg, 256, GEMMH_SMEM_BYTES>>>(Xh, Wt1, bb0, XpB);
    zero_kernel<<<128, 256>>>();
    fused_scan<<<128, 256, FS_SMEM_BYTES>>>(fW0, fW1, bW0, bW1, fb1, bb1,
                                            XpF, XpB, out);
}

// round 12
// speedup vs baseline: 3.9387x; 1.0789x over previous
#include <cuda_runtime.h>
#include <cuda_fp16.h>
#include <cuda_bf16.h>

#define T_SEQ 2048
#define NBATCH 16
#define DM 1024
#define HH 512

// ---------------- device scratch ----------------
__device__ __half g_Xh[(size_t)T_SEQ * NBATCH * DM];
__device__ __half g_Wt[2][(size_t)2048 * DM];
__device__ float g_XpF[(size_t)T_SEQ * NBATCH * 2048];
__device__ float g_XpB[(size_t)T_SEQ * NBATCH * 2048];
__device__ __half g_h0[2][2][NBATCH * HH];
__device__ __half g_h1[2][2][NBATCH * HH];
__device__ unsigned g_cnt[2];

// ---------------- helpers ----------------
__device__ __forceinline__ void mma16h(float c[4], uint4 a, unsigned b0, unsigned b1) {
    asm volatile(
        "mma.sync.aligned.m16n8k16.row.col.f32.f16.f16.f32 "
        "{%0,%1,%2,%3},{%4,%5,%6,%7},{%8,%9},{%0,%1,%2,%3};"
        : "+f"(c[0]), "+f"(c[1]), "+f"(c[2]), "+f"(c[3])
        : "r"(a.x), "r"(a.y), "r"(a.z), "r"(a.w), "r"(b0), "r"(b1));
}

__device__ __forceinline__ void cpasync16(void* s, const void* g) {
    unsigned ss = (unsigned)__cvta_generic_to_shared(s);
    asm volatile("cp.async.ca.shared.global [%0], [%1], 16;" :: "r"(ss), "l"(g));
}
__device__ __forceinline__ void cp_commit() { asm volatile("cp.async.commit_group;"); }
__device__ __forceinline__ void cp_wait2() { asm volatile("cp.async.wait_group 2;"); }

__device__ __forceinline__ float sigm(float x) { return 1.f / (1.f + __expf(-x)); }
__device__ __forceinline__ float tanh_(float x) {
    float xc = fminf(fmaxf(x, -20.f), 20.f);
    float e = __expf(-2.f * xc);
    return (1.f - e) / (1.f + e);
}

// ---------------- embedding gather (fp16 output) ----------------
__global__ void __launch_bounds__(256) embed_kernel(
    const int* __restrict__ ids, const float* __restrict__ tab, __half* __restrict__ Xh) {
    int i = blockIdx.x * 256 + threadIdx.x;
    int q = i & 127, row = i >> 7;
    int b = row & 15, t = row >> 4;
    int id = ids[b * T_SEQ + t];
    const float4* src = reinterpret_cast<const float4*>(tab) + (size_t)id * 256 + q * 2;
    float4 v0 = src[0], v1 = src[1];
    __half2 h0 = __floats2half2_rn(v0.x, v0.y);
    __half2 h1 = __floats2half2_rn(v0.z, v0.w);
    __half2 h2 = __floats2half2_rn(v1.x, v1.y);
    __half2 h3 = __floats2half2_rn(v1.z, v1.w);
    uint4 out;
    out.x = *(unsigned*)&h0; out.y = *(unsigned*)&h1;
    out.z = *(unsigned*)&h2; out.w = *(unsigned*)&h3;
    reinterpret_cast<uint4*>(Xh)[(size_t)row * 128 + q] = out;
}

// ---------------- W0 -> fp16 transposed [n][k] ----------------
__global__ void __launch_bounds__(256) wconv_kernel(
    const float* __restrict__ fW0, const float* __restrict__ bW0) {
    int idx = blockIdx.x * 256 + threadIdx.x;
    int n = idx & 2047;
    int k = (idx >> 11) & 1023;
    int d = idx >> 21;
    const float* src = d ? bW0 : fW0;
    g_Wt[d][(size_t)n * 1024 + k] = __float2half(src[(size_t)k * 2048 + n]);
}

// ---------------- pipelined FP16 GEMM (layer-0 input preactivations) ----------------
#define HA_STRIDE 40
#define HA_TILE (128 * HA_STRIDE)
#define GEMMH_SMEM_BYTES (6 * HA_TILE * 2)

__global__ void __launch_bounds__(256) gemmh_kernel(
    const __half* __restrict__ Xh, const __half* __restrict__ Wt,
    const float* __restrict__ bias, float* __restrict__ C) {
    extern __shared__ __align__(16) __half hsm[];
    __half* Ah = hsm;
    __half* Bh = hsm + 3 * HA_TILE;
    const int tid = threadIdx.x, lane = tid & 31, warp = tid >> 5;
    const int wm = warp >> 2, wn = warp & 3;
    const int gid = lane >> 2, tig = lane & 3;
    const int r0 = blockIdx.x * 128, n0 = blockIdx.y * 128;
    float acc[4][4][4] = {};

    const int c0r = tid >> 2, c0q = (tid & 3) * 8;
    const int c1r = (tid + 256) >> 2, c1q = ((tid + 256) & 3) * 8;

#define COPY_H(s, kt)                                                                      \
    do {                                                                                   \
        int k0_ = (kt) << 5;                                                               \
        cpasync16(Ah + (s) * HA_TILE + c0r * HA_STRIDE + c0q,                              \
                  Xh + (size_t)(r0 + c0r) * 1024 + k0_ + c0q);                             \
        cpasync16(Ah + (s) * HA_TILE + c1r * HA_STRIDE + c1q,                              \
                  Xh + (size_t)(r0 + c1r) * 1024 + k0_ + c1q);                             \
        cpasync16(Bh + (s) * HA_TILE + c0r * HA_STRIDE + c0q,                              \
                  Wt + (size_t)(n0 + c0r) * 1024 + k0_ + c0q);                             \
        cpasync16(Bh + (s) * HA_TILE + c1r * HA_STRIDE + c1q,                              \
                  Wt + (size_t)(n0 + c1r) * 1024 + k0_ + c1q);                             \
    } while (0)

    COPY_H(0, 0); cp_commit();
    COPY_H(1, 1); cp_commit();
    COPY_H(2, 2); cp_commit();

    for (int t = 0; t < 32; ++t) {
        int s = t % 3;
        const __half* Asb = Ah + s * HA_TILE;
        const __half* Bsb = Bh + s * HA_TILE;
        cp_wait2();
        __syncthreads();
#pragma unroll
        for (int kk = 0; kk < 32; kk += 16) {
            uint4 a[4];
            unsigned bb[4][2];
#pragma unroll
            for (int mt = 0; mt < 4; ++mt) {
                int m = wm * 64 + mt * 16;
                a[mt].x = *(const unsigned*)(Asb + (m + gid) * HA_STRIDE + kk + 2 * tig);
                a[mt].y = *(const unsigned*)(Asb + (m + gid + 8) * HA_STRIDE + kk + 2 * tig);
                a[mt].z = *(const unsigned*)(Asb + (m + gid) * HA_STRIDE + kk + 2 * tig + 8);
                a[mt].w = *(const unsigned*)(Asb + (m + gid + 8) * HA_STRIDE + kk + 2 * tig + 8);
            }
#pragma unroll
            for (int nt = 0; nt < 4; ++nt) {
                int n = wn * 32 + nt * 8 + gid;
                bb[nt][0] = *(const unsigned*)(Bsb + n * HA_STRIDE + kk + 2 * tig);
                bb[nt][1] = *(const unsigned*)(Bsb + n * HA_STRIDE + kk + 2 * tig + 8);
            }
#pragma unroll
            for (int mt = 0; mt < 4; ++mt)
#pragma unroll
                for (int nt = 0; nt < 4; ++nt)
                    mma16h(acc[mt][nt], a[mt], bb[nt][0], bb[nt][1]);
        }
        __syncthreads();
        if (t + 3 < 32) COPY_H(s, t + 3);
        cp_commit();
    }
#undef COPY_H

#pragma unroll
    for (int mt = 0; mt < 4; ++mt) {
#pragma unroll
        for (int nt = 0; nt < 4; ++nt) {
#pragma unroll
            for (int e = 0; e < 4; ++e) {
                int row = r0 + wm * 64 + mt * 16 + gid + ((e >> 1) * 8);
                int col = n0 + wn * 32 + nt * 8 + 2 * tig + (e & 1);
                float v = acc[mt][nt][e] + bias[col];
                int tt = row >> 4, b = row & 15;
                int gt = col >> 9, u = col & 511;
                size_t addr = (((size_t)tt * 32 + (u >> 4)) * 64 + gt * 16 + (u & 15)) * 16 + b;
                C[addr] = v;
            }
        }
    }
}

// ---------------- zero exchange/barrier state ----------------
__global__ void __launch_bounds__(256) zero_kernel() {
    int i = blockIdx.x * 256 + threadIdx.x;
    if (i < 16384) ((unsigned*)g_h0)[i] = 0u;
    if (i < 16384) ((unsigned*)g_h1)[i] = 0u;
    if (i < 2) g_cnt[i] = 0u;
}

// ---------------- fused layer-pipelined persistent scan ----------------
// Transposed recurrent GEMM: gates^T (m=16 batch, n=64 gate cols) =
//   h (A, via ldmatrix from smem) @ W (B, STATIC IN REGISTERS).
// 8 warps = 2 (n: 32 cols each) x 4 (k-split). Partials to 4 smem buffers.
#define FS_WA_BYTES 131072
#define FS_HS_BYTES 33536
#define FS_GB_BYTES 20480
#define FS_SMEM_BYTES (FS_WA_BYTES + FS_HS_BYTES + FS_GB_BYTES)

template <int ROLE>
__device__ __forceinline__ void scan_loop(
    const unsigned* __restrict__ Wa, __half* hs, float* Gb,
    const float* __restrict__ Xp, float* __restrict__ out,
    unsigned* bar, int dir, int blk, int u0,
    float bi, float bg, float bf, float bo) {
    constexpr int NKS = ROLE ? 16 : 8;       // k16 iters per k-split warp
    constexpr int KSLICE = NKS * 16;
    constexpr int HSTR = ROLE ? 1048 : 520;  // hs row stride (halves), conflict-free

    const int tid = threadIdx.x, lane = tid & 31, warp = tid >> 5;
    const int nt = warp & 1, kt = warp >> 1;
    const int tig = lane & 3, gid = lane >> 2;
    const int ej = tid & 15, eb = tid >> 4;
    const int q = tid & 63;
    const int b0_ = tid >> 6;

    // static weight B fragments -> registers (loop-invariant across all steps)
    unsigned Breg[NKS][4][2];
    {
        const unsigned* base = Wa + (warp * NKS * 8) * 32 + lane;
#pragma unroll
        for (int ks = 0; ks < NKS; ++ks)
#pragma unroll
            for (int j = 0; j < 4; ++j) {
                Breg[ks][j][0] = base[(ks * 8 + j * 2 + 0) * 32];
                Breg[ks][j][1] = base[(ks * 8 + j * 2 + 1) * 32];
            }
    }

    // per-lane ldmatrix.x4 base address for the A (h) fragment
    unsigned hs_base = (unsigned)__cvta_generic_to_shared(hs)
                     + ((lane & 15) * HSTR + (lane >> 4) * 8 + kt * KSLICE) * 2;

    float c_state = 0.f;
    float* Gp = Gb + kt * 1280;

    for (int s = 0; s <= T_SEQ; ++s) {
        const bool active = ROLE ? (s >= 1) : (s < T_SEQ);
        float h = 0.f;
        if (active) {
            float xi = 0.f, xg = 0.f, xf = 0.f, xo = 0.f;
            if (!ROLE) {
                int t = dir ? (T_SEQ - 1 - s) : s;
                const float* xp = Xp + ((size_t)t * 32 + blk) * 1024;
                xi = xp[(0 * 16 + ej) * 16 + eb];
                xg = xp[(1 * 16 + ej) * 16 + eb];
                xf = xp[(2 * 16 + ej) * 16 + eb];
                xo = xp[(3 * 16 + ej) * 16 + eb];
            }

            // stage h0 (and h1 for role1) into smem rows [batch][k]
            const uint4* h0src = (const uint4*)g_h0[dir][s & 1];
#pragma unroll
            for (int i = 0; i < 4; ++i) {
                int b = b0_ + i * 4;
                *(uint4*)(hs + b * HSTR + q * 8) = h0src[b * 64 + q];
            }
            if (ROLE) {
                const uint4* h1src = (const uint4*)g_h1[dir][s & 1];
#pragma unroll
                for (int i = 0; i < 4; ++i) {
                    int b = b0_ + i * 4;
                    *(uint4*)(hs + b * HSTR + 512 + q * 8) = h1src[b * 64 + q];
                }
            }
            __syncthreads();

            // gates^T = h @ W : A from ldmatrix, B static in regs
            float c[4][4] = {};
#pragma unroll
            for (int ks = 0; ks < NKS; ++ks) {
                unsigned a0, a1, a2, a3;
                asm volatile(
                    "ldmatrix.sync.aligned.m8n8.x4.shared.b16 {%0,%1,%2,%3}, [%4];"
                    : "=r"(a0), "=r"(a1), "=r"(a2), "=r"(a3)
                    : "r"(hs_base + ks * 32));
                uint4 a = {a0, a1, a2, a3};
#pragma unroll
                for (int j = 0; j < 4; ++j)
                    mma16h(c[j], a, Breg[ks][j][0], Breg[ks][j][1]);
            }

            // partial store (stride-20 pad -> conflict-free)
#pragma unroll
            for (int j = 0; j < 4; ++j) {
                int nb = nt * 32 + j * 8 + 2 * tig;
                Gp[nb * 20 + gid] = c[j][0];
                Gp[(nb + 1) * 20 + gid] = c[j][1];
                Gp[nb * 20 + gid + 8] = c[j][2];
                Gp[(nb + 1) * 20 + gid + 8] = c[j][3];
            }
            __syncthreads();

            float gi = xi + bi, gg = xg + bg, gf = xf + bf, go = xo + bo;
#pragma unroll
            for (int ktt = 0; ktt < 4; ++ktt) {
                const float* Gk = Gb + ktt * 1280;
                gi += Gk[(0 * 16 + ej) * 20 + eb];
                gg += Gk[(1 * 16 + ej) * 20 + eb];
                gf += Gk[(2 * 16 + ej) * 20 + eb];
                go += Gk[(3 * 16 + ej) * 20 + eb];
            }
            float fgate = sigm(gf + 1.0f);
            c_state = fgate * c_state + sigm(gi) * tanh_(gg);
            h = sigm(go) * tanh_(c_state);

            if (!ROLE)
                g_h0[dir][(s + 1) & 1][eb * 512 + u0 + ej] = __float2half(h);
            else
                g_h1[dir][(s + 1) & 1][eb * 512 + u0 + ej] = __float2half(h);
        }

        // inter-block barrier; out-store overlapped with the wait
        __threadfence();
        __syncthreads();
        if (tid == 0) atomicAdd(bar, 1u);
        if (ROLE && active) {
            int t1 = dir ? (T_SEQ - s) : (s - 1);
            out[((size_t)eb * 2048 + t1) * 1024 + dir * 512 + u0 + ej] = h;
        }
        if (tid == 0) {
            unsigned tgt = 64u * (unsigned)(s + 1);
            volatile unsigned* p = bar;
            while (*p < tgt) {}
        }
        __syncthreads();
        __threadfence();
    }
}

__global__ void __launch_bounds__(256, 1) fused_scan(
    const float* __restrict__ fW0, const float* __restrict__ fW1,
    const float* __restrict__ bW0, const float* __restrict__ bW1,
    const float* __restrict__ fb1, const float* __restrict__ bb1,
    const float* __restrict__ XpF, const float* __restrict__ XpB,
    float* __restrict__ out) {
    extern __shared__ __align__(16) char smraw[];
    unsigned* Wa = (unsigned*)smraw;
    __half* hs = (__half*)(smraw + FS_WA_BYTES);
    float* Gb = (float*)(smraw + FS_WA_BYTES + FS_HS_BYTES);

    const int bid = blockIdx.x;
    const int dir = bid >> 6;
    const int role = (bid >> 5) & 1;
    const int blk = bid & 31;
    const int u0 = blk * 16;

    const int NKS = role ? 16 : 8;
    const int KSLICE = NKS * 16;
    const int kbase = role ? 0 : 1024;
    const float* Wsrc = role ? (dir ? bW1 : fW1) : (dir ? bW0 : fW0);
    const float* Xp = dir ? XpB : XpF;

    const int tid = threadIdx.x;

    // stage weights into fragment-order smem (one-time), then regs in scan_loop
    const int total = 2048 * NKS;
    const int nks_shift = role ? 4 : 3;
    for (int idx = tid; idx < total; idx += 256) {
        int lane = idx & 31;
        int r = (idx >> 5) & 1;
        int j = (idx >> 6) & 3;
        int rest = idx >> 8;
        int ks = rest & (NKS - 1);
        int w = rest >> nks_shift;
        int ntl = w & 1, ktl = w >> 1;
        int lgid = lane >> 2, ltig = lane & 3;
        int k = kbase + ktl * KSLICE + ks * 16 + 2 * ltig + r * 8;
        int nl = ntl * 32 + j * 8 + lgid;
        int col = ((nl >> 4) << 9) + u0 + (nl & 15);
        __half2 v = __floats2half2_rn(Wsrc[(size_t)k * 2048 + col],
                                      Wsrc[(size_t)(k + 1) * 2048 + col]);
        Wa[idx] = *(unsigned*)&v;
    }
    __syncthreads();

    float bi = 0.f, bg = 0.f, bf = 0.f, bo = 0.f;
    if (role) {
        const float* bias = dir ? bb1 : fb1;
        int ej = tid & 15;
        bi = bias[0 * 512 + u0 + ej];
        bg = bias[1 * 512 + u0 + ej];
        bf = bias[2 * 512 + u0 + ej];
        bo = bias[3 * 512 + u0 + ej];
    }

    unsigned* bar = &g_cnt[dir];
    if (role)
        scan_loop<1>(Wa, hs, Gb, Xp, out, bar, dir, blk, u0, bi, bg, bf, bo);
    else
        scan_loop<0>(Wa, hs, Gb, Xp, out, bar, dir, blk, u0, bi, bg, bf, bo);
}

// ---------------- launch ----------------
extern "C" void kernel_launch(void* const* d_in, const int* in_sizes, int n_in,
                              void* d_out, int out_size) {
    const int* ids = (const int*)d_in[0];
    const float* tab = (const float*)d_in[1];
    const float* fW0 = (const float*)d_in[2];
    const float* fb0 = (const float*)d_in[3];
    const float* fW1 = (const float*)d_in[4];
    const float* fb1 = (const float*)d_in[5];
    const float* bW0 = (const float*)d_in[6];
    const float* bb0 = (const float*)d_in[7];
    const float* bW1 = (const float*)d_in[8];
    const float* bb1 = (const float*)d_in[9];
    float* out = (float*)d_out;

    cudaFuncSetAttribute(fused_scan, cudaFuncAttributeMaxDynamicSharedMemorySize,
                         FS_SMEM_BYTES);
    cudaFuncSetAttribute(gemmh_kernel, cudaFuncAttributeMaxDynamicSharedMemorySize,
                         GEMMH_SMEM_BYTES);

    __half *Xh, *Wt0, *Wt1;
    float *XpF, *XpB;
    cudaGetSymbolAddress((void**)&Xh, g_Xh);
    cudaGetSymbolAddress((void**)&Wt0, g_Wt);
    Wt1 = Wt0 + (size_t)2048 * 1024;
    cudaGetSymbolAddress((void**)&XpF, g_XpF);
    cudaGetSymbolAddress((void**)&XpB, g_XpB);

    embed_kernel<<<(T_SEQ * NBATCH * 128) / 256, 256>>>(ids, tab, Xh);
    wconv_kernel<<<(2 * 2048 * 1024) / 256, 256>>>(fW0, bW0);

    dim3 gg(256, 16);
    gemmh_kernel<<<gg, 256, GEMMH_SMEM_BYTES>>>(Xh, Wt0, fb0, XpF);
    gemmh_kernel<<<gg, 256, GEMMH_SMEM_BYTES>>>(Xh, Wt1, bb0, XpB);
    zero_kernel<<<128, 256>>>();
    fused_scan<<<128, 256, FS_SMEM_BYTES>>>(fW0, fW1, bW0, bW1, fb1, bb1,
                                            XpF, XpB, out);
}